// round 8
// baseline (speedup 1.0000x reference)
#include <cuda_runtime.h>
#include <cuda_bf16.h>
#include <cstdint>
#include <math.h>

#define B_ROWS 8192
#define F_DIM  2048
#define F2_DIM 4096
#define DB 512
#define DA 256
#define DE 256
#define DM 512
#define DS 512

// ---- device scratch (allocation forbidden) ----
__device__ __align__(256) int8_t g_c_hi[B_ROWS * F_DIM];
__device__ __align__(256) int8_t g_c_lo[B_ROWS * F_DIM];
__device__ __align__(256) int8_t g_a_hi[B_ROWS * F2_DIM];
__device__ __align__(256) int8_t g_a_lo[B_ROWS * F2_DIM];
__device__ __align__(256) float g_f32a [B_ROWS * F_DIM];
__device__ __align__(256) float g_f32b [B_ROWS * F_DIM];
__device__ __align__(256) float g_fused[B_ROWS * F_DIM];
__device__ __align__(256) int8_t g_wq[4 * F_DIM * F_DIM];
__device__ __align__(256) int8_t g_w1h[F2_DIM * F_DIM];
__device__ __align__(256) int8_t g_w1l[F2_DIM * F_DIM];
__device__ __align__(256) int8_t g_w2h[F_DIM * F2_DIM];
__device__ __align__(256) int8_t g_w2l[F_DIM * F2_DIM];
__device__ float g_partials[4 * 64];
__device__ float g_pmax[2 * 64];
__device__ float g_scale[4];
__device__ float g_winv[2];

// ---- helpers (baseline PTX only) ----
__device__ __forceinline__ uint32_t smem_u32(const void* p) {
    uint32_t a;
    asm("{ .reg .u64 t; cvta.to.shared.u64 t, %1; cvt.u32.u64 %0, t; }" : "=r"(a) : "l"(p));
    return a;
}
__device__ __forceinline__ uint32_t sw128(uint32_t x) { return x ^ ((x >> 3) & 0x70); }
__device__ __forceinline__ void cp16(uint32_t dst, const void* src) {
    asm volatile("cp.async.cg.shared.global [%0], [%1], 16;\n" :: "r"(dst), "l"(src) : "memory");
}
__device__ __forceinline__ void cp_commit() { asm volatile("cp.async.commit_group;\n" ::: "memory"); }
template <int N> __device__ __forceinline__ void cp_wait() {
    asm volatile("cp.async.wait_group %0;\n" :: "n"(N) : "memory");
}
__device__ __forceinline__ void ldsm4(uint32_t* r, uint32_t a) {
    asm volatile("ldmatrix.sync.aligned.m8n8.x4.shared.b16 {%0,%1,%2,%3}, [%4];"
        : "=r"(r[0]), "=r"(r[1]), "=r"(r[2]), "=r"(r[3]) : "r"(a));
}
__device__ __forceinline__ void mma_s8(int* c, const uint32_t* a, uint32_t b0, uint32_t b1) {
    asm volatile("mma.sync.aligned.m16n8k32.row.col.s32.s8.s8.s32 "
        "{%0,%1,%2,%3}, {%4,%5,%6,%7}, {%8,%9}, {%0,%1,%2,%3};"
        : "+r"(c[0]), "+r"(c[1]), "+r"(c[2]), "+r"(c[3])
        : "r"(a[0]), "r"(a[1]), "r"(a[2]), "r"(a[3]), "r"(b0), "r"(b1));
}
__device__ __forceinline__ float gelu_erf(float h) {
    return 0.5f * h * (1.0f + erff(h * 0.70710678f));
}
// quantize to 16-bit fixed point (S = 4096) -> int8 hi/lo limbs
__device__ __forceinline__ void q16(float g, int& hi, int& lo) {
    int v = __float2int_rn(g * 4096.f);
    v = v < -32512 ? -32512 : (v > 32512 ? 32512 : v);
    lo = (int)(int8_t)(v & 0xFF);
    hi = (v - lo) >> 8;
}

// ---- int8 GEMM: acc_sel(p) += A_p[M,K] @ B_p[N,K]^T ; y = (acc0*C0 + acc1*C1)*s + bias ----
#define TILE_M 128
#define TILE_N 128
#define TILE_K 128
#define STAGE_BYTES (TILE_M * 128 + TILE_N * 128)   // 32KB
#define STAGES 3
#define GEMM_SMEM_DYN (STAGES * STAGE_BYTES + 1024)

__device__ __forceinline__ void load_tiles8(uint32_t sa, uint32_t sb,
        const int8_t* A, const int8_t* Bm, int m0, int n0, int k0, int K, int tid) {
    const char* ab = (const char*)(A + (size_t)m0 * K + k0);
    const char* bb = (const char*)(Bm + (size_t)n0 * K + k0);
#pragma unroll
    for (int i = 0; i < 4; i++) {
        int t = tid + i * 256, row = t >> 3, ch = t & 7;
        cp16(sa + sw128(row * 128 + ch * 16), ab + (size_t)row * K + ch * 16);
    }
#pragma unroll
    for (int i = 0; i < 4; i++) {
        int t = tid + i * 256, row = t >> 3, ch = t & 7;
        cp16(sb + sw128(row * 128 + ch * 16), bb + (size_t)row * K + ch * 16);
    }
}

__device__ __forceinline__ void mma_block(int acc[4][4][4], uint32_t a[4][4], uint32_t b[2][4]) {
#pragma unroll
    for (int mi = 0; mi < 4; ++mi)
#pragma unroll
        for (int n8 = 0; n8 < 4; ++n8)
            mma_s8(acc[mi][n8], a[mi], b[n8 >> 1][(n8 & 1) * 2], b[n8 >> 1][(n8 & 1) * 2 + 1]);
}

template <int EPI>  // 0: gelu -> int8 hi/lo; 1: fp32 out
__global__ void __launch_bounds__(256)
gemm_i8(const int8_t* A0, const int8_t* A1, const int8_t* A2,
        const int8_t* B0, const int8_t* B1, const int8_t* B2,
        int n_pass, int sel_mask, int N, int K,
        float C0, float C1,
        const float* scale_ptr, const float* __restrict__ bias,
        float* outF, int8_t* outH8, int8_t* outL8) {
    extern __shared__ char smem[];
    uint32_t sbase = (smem_u32(smem) + 1023) & ~1023u;
    int tid = threadIdx.x, wid = tid >> 5, lane = tid & 31;
    int n0 = blockIdx.x * TILE_N, m0 = blockIdx.y * TILE_M;
    int wm = wid & 1, wn = wid >> 1;
    const int8_t* Al[3] = {A0, A1, A2};
    const int8_t* Bl[3] = {B0, B1, B2};
    const int KT = K / TILE_K;
    const int iters = n_pass * KT;

    for (int p = 0; p < 2 && p < iters; ++p) {
        int sp = p / KT, kk = (p % KT) * TILE_K;
        uint32_t st = sbase + p * STAGE_BYTES;
        load_tiles8(st, st + TILE_M * 128, Al[sp], Bl[sp], m0, n0, kk, K, tid);
        cp_commit();
    }

    int acc0[4][4][4], acc1[4][4][4];
#pragma unroll
    for (int i = 0; i < 4; i++)
#pragma unroll
        for (int j = 0; j < 4; j++)
#pragma unroll
            for (int k = 0; k < 4; k++) { acc0[i][j][k] = 0; acc1[i][j][k] = 0; }

    int q = lane >> 3, r = lane & 7;
    int aRow = wm * 64 + r + (q & 1) * 8;
    int aCol = (q >> 1) * 16;
    int bRow = wn * 32 + r + (q >> 1) * 8;
    int bCol = (q & 1) * 16;

    for (int it = 0; it < iters; ++it) {
        cp_wait<1>();
        __syncthreads();
        if (it + 2 < iters) {
            int nit = it + 2, sp = nit / KT, kk = (nit % KT) * TILE_K;
            uint32_t st = sbase + (nit % STAGES) * STAGE_BYTES;
            load_tiles8(st, st + TILE_M * 128, Al[sp], Bl[sp], m0, n0, kk, K, tid);
        }
        cp_commit();
        uint32_t sA = sbase + (it % STAGES) * STAGE_BYTES;
        uint32_t sB = sA + TILE_M * 128;
        int sel = (sel_mask >> (it / KT)) & 1;
#pragma unroll
        for (int ks = 0; ks < 4; ++ks) {
            uint32_t a[4][4], b[2][4];
#pragma unroll
            for (int mi = 0; mi < 4; ++mi)
                ldsm4(a[mi], sA + sw128((aRow + mi * 16) * 128 + aCol + ks * 32));
#pragma unroll
            for (int nj = 0; nj < 2; ++nj)
                ldsm4(b[nj], sB + sw128((bRow + nj * 16) * 128 + bCol + ks * 32));
            if (sel == 0) mma_block(acc0, a, b);
            else          mma_block(acc1, a, b);
        }
    }

    float s = scale_ptr ? *scale_ptr : 1.0f;
    int group = lane >> 2, tg = lane & 3;
#pragma unroll
    for (int mi = 0; mi < 4; ++mi) {
#pragma unroll
        for (int n8 = 0; n8 < 4; ++n8) {
            int row = m0 + wm * 64 + mi * 16 + group;
            int col = n0 + wn * 32 + n8 * 8 + tg * 2;
            float bb0 = bias[col], bb1 = bias[col + 1];
            float y0 = fmaf((float)acc0[mi][n8][0] * C0 + (float)acc1[mi][n8][0] * C1, s, bb0);
            float y1 = fmaf((float)acc0[mi][n8][1] * C0 + (float)acc1[mi][n8][1] * C1, s, bb1);
            float y2 = fmaf((float)acc0[mi][n8][2] * C0 + (float)acc1[mi][n8][2] * C1, s, bb0);
            float y3 = fmaf((float)acc0[mi][n8][3] * C0 + (float)acc1[mi][n8][3] * C1, s, bb1);
            if (EPI == 0) {
                int h0, l0, h1, l1, h2, l2, h3, l3;
                q16(gelu_erf(y0), h0, l0); q16(gelu_erf(y1), h1, l1);
                q16(gelu_erf(y2), h2, l2); q16(gelu_erf(y3), h3, l3);
                *(int16_t*)&outH8[(size_t)row * N + col]       = (int16_t)((h0 & 0xFF) | ((h1 & 0xFF) << 8));
                *(int16_t*)&outH8[(size_t)(row + 8) * N + col] = (int16_t)((h2 & 0xFF) | ((h3 & 0xFF) << 8));
                *(int16_t*)&outL8[(size_t)row * N + col]       = (int16_t)((l0 & 0xFF) | ((l1 & 0xFF) << 8));
                *(int16_t*)&outL8[(size_t)(row + 8) * N + col] = (int16_t)((l2 & 0xFF) | ((l3 & 0xFF) << 8));
            } else {
                *(float2*)&outF[(size_t)row * N + col]       = make_float2(y0, y1);
                *(float2*)&outF[(size_t)(row + 8) * N + col] = make_float2(y2, y3);
            }
        }
    }
}

// ---- elementwise kernels ----
__device__ __forceinline__ float warpSum(float x) {
#pragma unroll
    for (int o = 16; o > 0; o >>= 1) x += __shfl_xor_sync(0xffffffffu, x, o);
    return x;
}
__device__ __forceinline__ float warpMax(float x) {
#pragma unroll
    for (int o = 16; o > 0; o >>= 1) x = fmaxf(x, __shfl_xor_sync(0xffffffffu, x, o));
    return x;
}

__global__ void absmean_partial(const float* w0, const float* w1, const float* w2, const float* w3) {
    const float* w = (blockIdx.y == 0) ? w0 : (blockIdx.y == 1) ? w1 : (blockIdx.y == 2) ? w2 : w3;
    const int chunk = (F_DIM * F_DIM) / 64;
    int base = blockIdx.x * chunk;
    float s = 0.f;
    for (int i = threadIdx.x; i < chunk; i += 256) s += fabsf(w[base + i]);
    __shared__ float red[8];
    s = warpSum(s);
    int wd = threadIdx.x >> 5, ln = threadIdx.x & 31;
    if (ln == 0) red[wd] = s;
    __syncthreads();
    if (wd == 0) {
        float v = (ln < 8) ? red[ln] : 0.f;
        v = warpSum(v);
        if (ln == 0) g_partials[blockIdx.y * 64 + blockIdx.x] = v;
    }
}

__global__ void quantize_ternary(const float* __restrict__ w, int8_t* __restrict__ kq, int slot) {
    float sum = 0.f;
#pragma unroll
    for (int i = 0; i < 64; i++) sum += g_partials[slot * 64 + i];
    float s = sum * (1.0f / (float)(F_DIM * F_DIM));
    if (blockIdx.x == 0 && threadIdx.x == 0) g_scale[slot] = s;
    float inv = 1.0f / (s + 1e-5f);
    int stride = gridDim.x * blockDim.x;
    for (int i = blockIdx.x * blockDim.x + threadIdx.x; i < F_DIM * F_DIM; i += stride) {
        float qv = rintf(fminf(fmaxf(w[i] * inv, -1.f), 1.f));
        kq[i] = (int8_t)(int)qv;
    }
}

__global__ void absmax_partial(const float* w0, const float* w1) {
    const float* w = blockIdx.y ? w1 : w0;
    const int chunk = (F2_DIM * F_DIM) / 64;
    int base = blockIdx.x * chunk;
    float m = 0.f;
    for (int i = threadIdx.x; i < chunk; i += 256) m = fmaxf(m, fabsf(w[base + i]));
    __shared__ float red[8];
    m = warpMax(m);
    int wd = threadIdx.x >> 5, ln = threadIdx.x & 31;
    if (ln == 0) red[wd] = m;
    __syncthreads();
    if (wd == 0) {
        float v = (ln < 8) ? red[ln] : 0.f;
        v = warpMax(v);
        if (ln == 0) g_pmax[blockIdx.y * 64 + blockIdx.x] = v;
    }
}

__global__ void quantize_w16(const float* __restrict__ w, int8_t* __restrict__ hi,
                             int8_t* __restrict__ lo, int slot, int n) {
    float m = 0.f;
#pragma unroll
    for (int i = 0; i < 64; i++) m = fmaxf(m, g_pmax[slot * 64 + i]);
    float Sw = 32512.f / m;
    if (blockIdx.x == 0 && threadIdx.x == 0) g_winv[slot] = m / 32512.f;
    int stride = gridDim.x * blockDim.x;
    for (int i = blockIdx.x * blockDim.x + threadIdx.x; i < n; i += stride) {
        int v = __float2int_rn(w[i] * Sw);
        v = v < -32512 ? -32512 : (v > 32512 ? 32512 : v);
        int l = (int)(int8_t)(v & 0xFF);
        lo[i] = (int8_t)l;
        hi[i] = (int8_t)((v - l) >> 8);
    }
}

__global__ void build_combined(const float* zb, const float* za, const float* ze,
                               const float* zm, const float* zs,
                               int8_t* __restrict__ ch, int8_t* __restrict__ cl) {
    int idx = blockIdx.x * 256 + threadIdx.x;
    int r = idx >> 9;
    int c4 = (idx & 511) * 4;
    const float* src; int off;
    if      (c4 < DB)                { src = zb; off = r * DB + c4; }
    else if (c4 < DB + DA)           { src = za; off = r * DA + (c4 - DB); }
    else if (c4 < DB + DA + DE)      { src = ze; off = r * DE + (c4 - DB - DA); }
    else if (c4 < DB + DA + DE + DM) { src = zm; off = r * DM + (c4 - DB - DA - DE); }
    else                             { src = zs; off = r * DS + (c4 - DB - DA - DE - DM); }
    float4 v = *reinterpret_cast<const float4*>(src + off);
    float vv[4] = {v.x, v.y, v.z, v.w};
    uint32_t ph = 0, pl = 0;
#pragma unroll
    for (int j = 0; j < 4; j++) {
        int h, l;
        q16(vv[j], h, l);
        ph |= (uint32_t)(h & 0xFF) << (j * 8);
        pl |= (uint32_t)(l & 0xFF) << (j * 8);
    }
    size_t o = (size_t)r * F_DIM + c4;
    *reinterpret_cast<uint32_t*>(&ch[o]) = ph;
    *reinterpret_cast<uint32_t*>(&cl[o]) = pl;
}

__global__ void fused_sig_ln(const float* __restrict__ g, const float* __restrict__ t,
                             const float* __restrict__ lg, const float* __restrict__ lb,
                             float* __restrict__ fused,
                             int8_t* __restrict__ fh, int8_t* __restrict__ fl) {
    int row = blockIdx.x;
    size_t base = (size_t)row * F_DIM;
    float v[8], s1 = 0.f, s2 = 0.f;
#pragma unroll
    for (int i = 0; i < 8; i++) {
        int c = i * 256 + threadIdx.x;
        float gg = g[base + c], tt = t[base + c];
        float f = tt / (1.0f + expf(-1.2f * gg));
        v[i] = f; s1 += f; s2 += f * f;
    }
    __shared__ float rs[8], rq[8];
    int wd = threadIdx.x >> 5, ln = threadIdx.x & 31;
    float a = warpSum(s1), b = warpSum(s2);
    if (ln == 0) { rs[wd] = a; rq[wd] = b; }
    __syncthreads();
    if (wd == 0) {
        float x = (ln < 8) ? rs[ln] : 0.f;
        float y = (ln < 8) ? rq[ln] : 0.f;
        x = warpSum(x); y = warpSum(y);
        if (ln == 0) { rs[0] = x; rq[0] = y; }
    }
    __syncthreads();
    float mean = rs[0] * (1.0f / F_DIM);
    float var = rq[0] * (1.0f / F_DIM) - mean * mean;
    float inv = rsqrtf(var + 1e-5f);
#pragma unroll
    for (int i = 0; i < 8; i++) {
        int c = i * 256 + threadIdx.x;
        float y = (v[i] - mean) * inv * lg[c] + lb[c];
        fused[base + c] = y;
        int h, l;
        q16(y, h, l);
        fh[base + c] = (int8_t)h;
        fl[base + c] = (int8_t)l;
    }
}

__global__ void final_ln(const float* __restrict__ fused, const float* __restrict__ mlp,
                         const float* __restrict__ lg, const float* __restrict__ lb,
                         float* __restrict__ out) {
    int row = blockIdx.x;
    size_t base = (size_t)row * F_DIM;
    float v[8], s1 = 0.f, s2 = 0.f;
#pragma unroll
    for (int i = 0; i < 8; i++) {
        int c = i * 256 + threadIdx.x;
        float f = fused[base + c] + mlp[base + c];
        v[i] = f; s1 += f; s2 += f * f;
    }
    __shared__ float rs[8], rq[8];
    int wd = threadIdx.x >> 5, ln = threadIdx.x & 31;
    float a = warpSum(s1), b = warpSum(s2);
    if (ln == 0) { rs[wd] = a; rq[wd] = b; }
    __syncthreads();
    if (wd == 0) {
        float x = (ln < 8) ? rs[ln] : 0.f;
        float y = (ln < 8) ? rq[ln] : 0.f;
        x = warpSum(x); y = warpSum(y);
        if (ln == 0) { rs[0] = x; rq[0] = y; }
    }
    __syncthreads();
    float mean = rs[0] * (1.0f / F_DIM);
    float var = rq[0] * (1.0f / F_DIM) - mean * mean;
    float inv = rsqrtf(var + 1e-5f);
#pragma unroll
    for (int i = 0; i < 8; i++) {
        int c = i * 256 + threadIdx.x;
        out[base + c] = (v[i] - mean) * inv * lg[c] + lb[c];
    }
}

// ---- launch ----
extern "C" void kernel_launch(void* const* d_in, const int* in_sizes, int n_in,
                              void* d_out, int out_size) {
    (void)in_sizes; (void)n_in; (void)out_size;
    const float* zb = (const float*)d_in[0];
    const float* za = (const float*)d_in[1];
    const float* ze = (const float*)d_in[2];
    const float* zm = (const float*)d_in[3];
    const float* zs = (const float*)d_in[4];
    const float* gate_w1 = (const float*)d_in[5];
    const float* gate_b1 = (const float*)d_in[6];
    const float* gate_w2 = (const float*)d_in[7];
    const float* gate_b2 = (const float*)d_in[8];
    const float* tr_w1 = (const float*)d_in[9];
    const float* tr_b1 = (const float*)d_in[10];
    const float* tr_w2 = (const float*)d_in[11];
    const float* tr_b2 = (const float*)d_in[12];
    const float* mlp_w1 = (const float*)d_in[13];
    const float* mlp_b1 = (const float*)d_in[14];
    const float* mlp_w2 = (const float*)d_in[15];
    const float* mlp_b2 = (const float*)d_in[16];
    const float* ln1_g = (const float*)d_in[17];
    const float* ln1_b = (const float*)d_in[18];
    const float* ln2_g = (const float*)d_in[19];
    const float* ln2_b = (const float*)d_in[20];
    float* out = (float*)d_out;

    int8_t *ch, *cl, *ah, *al, *wqb, *w1h, *w1l, *w2h, *w2l;
    float *fa, *fb, *fu, *scb, *winv;
    cudaGetSymbolAddress((void**)&ch,  g_c_hi);
    cudaGetSymbolAddress((void**)&cl,  g_c_lo);
    cudaGetSymbolAddress((void**)&ah,  g_a_hi);
    cudaGetSymbolAddress((void**)&al,  g_a_lo);
    cudaGetSymbolAddress((void**)&wqb, g_wq);
    cudaGetSymbolAddress((void**)&w1h, g_w1h);
    cudaGetSymbolAddress((void**)&w1l, g_w1l);
    cudaGetSymbolAddress((void**)&w2h, g_w2h);
    cudaGetSymbolAddress((void**)&w2l, g_w2l);
    cudaGetSymbolAddress((void**)&fa,  g_f32a);
    cudaGetSymbolAddress((void**)&fb,  g_f32b);
    cudaGetSymbolAddress((void**)&fu,  g_fused);
    cudaGetSymbolAddress((void**)&scb, g_scale);
    cudaGetSymbolAddress((void**)&winv, g_winv);
    int8_t* wq0 = wqb;
    int8_t* wq1 = wqb + (size_t)F_DIM * F_DIM;
    int8_t* wq2 = wqb + 2 * (size_t)F_DIM * F_DIM;
    int8_t* wq3 = wqb + 3 * (size_t)F_DIM * F_DIM;

    cudaFuncSetAttribute(gemm_i8<0>, cudaFuncAttributeMaxDynamicSharedMemorySize, GEMM_SMEM_DYN);
    cudaFuncSetAttribute(gemm_i8<1>, cudaFuncAttributeMaxDynamicSharedMemorySize, GEMM_SMEM_DYN);

    // combine coefficients: activations are 16-bit fixed point with S=4096
    const float TC0 = 256.f / 4096.f;   // ternary: hi limb
    const float TC1 = 1.f / 4096.f;     // ternary: lo limb
    const float MC0 = 65536.f / 4096.f; // mlp: xh*wh
    const float MC1 = 256.f / 4096.f;   // mlp: xh*wl + xl*wh

    // weight prep
    absmean_partial<<<dim3(64, 4), 256>>>(gate_w1, gate_w2, tr_w1, tr_w2);
    quantize_ternary<<<256, 256>>>(gate_w1, wq0, 0);
    quantize_ternary<<<256, 256>>>(gate_w2, wq1, 1);
    quantize_ternary<<<256, 256>>>(tr_w1, wq2, 2);
    quantize_ternary<<<256, 256>>>(tr_w2, wq3, 3);
    absmax_partial<<<dim3(64, 2), 256>>>(mlp_w1, mlp_w2);
    quantize_w16<<<512, 256>>>(mlp_w1, w1h, w1l, 0, F2_DIM * F_DIM);
    quantize_w16<<<512, 256>>>(mlp_w2, w2h, w2l, 1, F_DIM * F2_DIM);
    build_combined<<<(B_ROWS * 512) / 256, 256>>>(zb, za, ze, zm, zs, ch, cl);

    dim3 g2048(F_DIM / TILE_N, B_ROWS / TILE_M);   // (16, 64)
    dim3 g4096(F2_DIM / TILE_N, B_ROWS / TILE_M);  // (32, 64)

    // gate path: pass0 = hi->acc0, pass1 = lo->acc1 (sel_mask 0b10)
    gemm_i8<0><<<g2048, 256, GEMM_SMEM_DYN>>>(ch, cl, nullptr, wq0, wq0, nullptr,
        2, 2, F_DIM, F_DIM, TC0, TC1, scb + 0, gate_b1, nullptr, ah, al);
    gemm_i8<1><<<g2048, 256, GEMM_SMEM_DYN>>>(ah, al, nullptr, wq1, wq1, nullptr,
        2, 2, F_DIM, F_DIM, TC0, TC1, scb + 1, gate_b2, fa, nullptr, nullptr);
    // transform path (act buffers free after gate2)
    gemm_i8<0><<<g2048, 256, GEMM_SMEM_DYN>>>(ch, cl, nullptr, wq2, wq2, nullptr,
        2, 2, F_DIM, F_DIM, TC0, TC1, scb + 2, tr_b1, nullptr, ah, al);
    gemm_i8<1><<<g2048, 256, GEMM_SMEM_DYN>>>(ah, al, nullptr, wq3, wq3, nullptr,
        2, 2, F_DIM, F_DIM, TC0, TC1, scb + 3, tr_b2, fb, nullptr, nullptr);
    // sigmoid-gate fuse + ln1 (fused fp32 + int8 hi/lo reusing comb buffers)
    fused_sig_ln<<<B_ROWS, 256>>>(fa, fb, ln1_g, ln1_b, fu, ch, cl);
    // mlp1: passes (xh*wh->acc0, xh*wl->acc1, xl*wh->acc1) => sel_mask 0b110
    gemm_i8<0><<<g4096, 256, GEMM_SMEM_DYN>>>(ch, ch, cl, w1h, w1l, w1h,
        3, 6, F2_DIM, F_DIM, MC0, MC1, winv + 0, mlp_b1, nullptr, ah, al);
    gemm_i8<1><<<g2048, 256, GEMM_SMEM_DYN>>>(ah, ah, al, w2h, w2l, w2h,
        3, 6, F_DIM, F2_DIM, MC0, MC1, winv + 1, mlp_b2, fa, nullptr, nullptr);
    // residual + ln2
    final_ln<<<B_ROWS, 256>>>(fu, fa, ln2_g, ln2_b, out);
}

// round 9
// speedup vs baseline: 1.0873x; 1.0873x over previous
#include <cuda_runtime.h>
#include <cuda_bf16.h>
#include <cstdint>
#include <math.h>

#define B_ROWS 8192
#define F_DIM  2048
#define F2_DIM 4096
#define DB 512
#define DA 256
#define DE 256
#define DM 512
#define DS 512

// ---- device scratch (allocation forbidden) ----
__device__ __align__(256) int8_t g_c_hi[B_ROWS * F_DIM];
__device__ __align__(256) int8_t g_c_lo[B_ROWS * F_DIM];
__device__ __align__(256) int8_t g_a_hi[B_ROWS * F2_DIM];
__device__ __align__(256) int8_t g_a_lo[B_ROWS * F2_DIM];
__device__ __align__(256) float g_f32a [B_ROWS * F_DIM];
__device__ __align__(256) float g_f32b [B_ROWS * F_DIM];
__device__ __align__(256) float g_fused[B_ROWS * F_DIM];
__device__ __align__(256) int8_t g_wq[4 * F_DIM * F_DIM];
__device__ __align__(256) int8_t g_w1h[F2_DIM * F_DIM];
__device__ __align__(256) int8_t g_w1l[F2_DIM * F_DIM];
__device__ __align__(256) int8_t g_w2h[F_DIM * F2_DIM];
__device__ __align__(256) int8_t g_w2l[F_DIM * F2_DIM];
__device__ float g_partials[4 * 64];
__device__ float g_pmax[2 * 64];
__device__ float g_scale[4];
__device__ float g_winv[2];

// ---- helpers (baseline PTX only) ----
__device__ __forceinline__ uint32_t smem_u32(const void* p) {
    uint32_t a;
    asm("{ .reg .u64 t; cvta.to.shared.u64 t, %1; cvt.u32.u64 %0, t; }" : "=r"(a) : "l"(p));
    return a;
}
__device__ __forceinline__ uint32_t sw128(uint32_t x) { return x ^ ((x >> 3) & 0x70); }
__device__ __forceinline__ void cp16(uint32_t dst, const void* src) {
    asm volatile("cp.async.cg.shared.global [%0], [%1], 16;\n" :: "r"(dst), "l"(src) : "memory");
}
__device__ __forceinline__ void cp_commit() { asm volatile("cp.async.commit_group;\n" ::: "memory"); }
template <int N> __device__ __forceinline__ void cp_wait() {
    asm volatile("cp.async.wait_group %0;\n" :: "n"(N) : "memory");
}
__device__ __forceinline__ void ldsm4(uint32_t* r, uint32_t a) {
    asm volatile("ldmatrix.sync.aligned.m8n8.x4.shared.b16 {%0,%1,%2,%3}, [%4];"
        : "=r"(r[0]), "=r"(r[1]), "=r"(r[2]), "=r"(r[3]) : "r"(a));
}
__device__ __forceinline__ void mma_s8(int* c, const uint32_t* a, uint32_t b0, uint32_t b1) {
    asm volatile("mma.sync.aligned.m16n8k32.row.col.s32.s8.s8.s32 "
        "{%0,%1,%2,%3}, {%4,%5,%6,%7}, {%8,%9}, {%0,%1,%2,%3};"
        : "+r"(c[0]), "+r"(c[1]), "+r"(c[2]), "+r"(c[3])
        : "r"(a[0]), "r"(a[1]), "r"(a[2]), "r"(a[3]), "r"(b0), "r"(b1));
}
__device__ __forceinline__ float gelu_erf(float h) {
    return 0.5f * h * (1.0f + erff(h * 0.70710678f));
}
// quantize to 16-bit fixed point (S = 4096) -> int8 hi/lo limbs
__device__ __forceinline__ void q16(float g, int& hi, int& lo) {
    int v = __float2int_rn(g * 4096.f);
    v = v < -32512 ? -32512 : (v > 32512 ? 32512 : v);
    lo = (int)(int8_t)(v & 0xFF);
    hi = (v - lo) >> 8;
}

// ---- int8 GEMM, Horner passes: acc = ((pass0)*256 + pass1 [+ pass2]); y = acc*C*s + bias ----
#define TILE_M 128
#define TILE_N 128
#define TILE_K 128
#define STAGE_BYTES (TILE_M * 128 + TILE_N * 128)   // 32KB
#define STAGES 3
#define GEMM_SMEM_DYN (STAGES * STAGE_BYTES + 1024)

__device__ __forceinline__ void load_tiles8(uint32_t sa, uint32_t sb,
        const int8_t* A, const int8_t* Bm, int m0, int n0, int k0, int K, int tid) {
    const char* ab = (const char*)(A + (size_t)m0 * K + k0);
    const char* bb = (const char*)(Bm + (size_t)n0 * K + k0);
#pragma unroll
    for (int i = 0; i < 4; i++) {
        int t = tid + i * 256, row = t >> 3, ch = t & 7;
        cp16(sa + sw128(row * 128 + ch * 16), ab + (size_t)row * K + ch * 16);
    }
#pragma unroll
    for (int i = 0; i < 4; i++) {
        int t = tid + i * 256, row = t >> 3, ch = t & 7;
        cp16(sb + sw128(row * 128 + ch * 16), bb + (size_t)row * K + ch * 16);
    }
}

template <int EPI>  // 0: gelu -> int8 hi/lo; 1: fp32 out
__global__ void __launch_bounds__(256, 2)
gemm_i8(const int8_t* A0, const int8_t* A1, const int8_t* A2,
        const int8_t* B0, const int8_t* B1, const int8_t* B2,
        int n_pass, int N, int K, float C0,
        const float* scale_ptr, const float* __restrict__ bias,
        float* outF, int8_t* outH8, int8_t* outL8) {
    extern __shared__ char smem[];
    uint32_t sbase = (smem_u32(smem) + 1023) & ~1023u;
    int tid = threadIdx.x, wid = tid >> 5, lane = tid & 31;
    int n0 = blockIdx.x * TILE_N, m0 = blockIdx.y * TILE_M;
    int wm = wid & 1, wn = wid >> 1;
    const int8_t* Al[3] = {A0, A1, A2};
    const int8_t* Bl[3] = {B0, B1, B2};
    const int KT = K / TILE_K;
    const int iters = n_pass * KT;

    for (int p = 0; p < 2 && p < iters; ++p) {
        int sp = p / KT, kk = (p % KT) * TILE_K;
        uint32_t st = sbase + p * STAGE_BYTES;
        load_tiles8(st, st + TILE_M * 128, Al[sp], Bl[sp], m0, n0, kk, K, tid);
        cp_commit();
    }

    int acc[4][4][4];
#pragma unroll
    for (int i = 0; i < 4; i++)
#pragma unroll
        for (int j = 0; j < 4; j++)
#pragma unroll
            for (int k = 0; k < 4; k++) acc[i][j][k] = 0;

    int q = lane >> 3, r = lane & 7;
    int aRow = wm * 64 + r + (q & 1) * 8;
    int aCol = (q >> 1) * 16;
    int bRow = wn * 32 + r + (q >> 1) * 8;
    int bCol = (q & 1) * 16;

    for (int it = 0; it < iters; ++it) {
        if (it == KT) {   // Horner: weight the hi-limb pass by 256 (exact int)
#pragma unroll
            for (int i = 0; i < 4; i++)
#pragma unroll
                for (int j = 0; j < 4; j++)
#pragma unroll
                    for (int k = 0; k < 4; k++) acc[i][j][k] <<= 8;
        }
        cp_wait<1>();
        __syncthreads();
        if (it + 2 < iters) {
            int nit = it + 2, sp = nit / KT, kk = (nit % KT) * TILE_K;
            uint32_t st = sbase + (nit % STAGES) * STAGE_BYTES;
            load_tiles8(st, st + TILE_M * 128, Al[sp], Bl[sp], m0, n0, kk, K, tid);
        }
        cp_commit();
        uint32_t sA = sbase + (it % STAGES) * STAGE_BYTES;
        uint32_t sB = sA + TILE_M * 128;
#pragma unroll
        for (int ks = 0; ks < 4; ++ks) {
            uint32_t a[4][4], b[2][4];
#pragma unroll
            for (int mi = 0; mi < 4; ++mi)
                ldsm4(a[mi], sA + sw128((aRow + mi * 16) * 128 + aCol + ks * 32));
#pragma unroll
            for (int nj = 0; nj < 2; ++nj)
                ldsm4(b[nj], sB + sw128((bRow + nj * 16) * 128 + bCol + ks * 32));
#pragma unroll
            for (int mi = 0; mi < 4; ++mi)
#pragma unroll
                for (int n8 = 0; n8 < 4; ++n8)
                    mma_s8(acc[mi][n8], a[mi],
                           b[n8 >> 1][(n8 & 1) * 2], b[n8 >> 1][(n8 & 1) * 2 + 1]);
        }
    }

    float s = (scale_ptr ? *scale_ptr : 1.0f) * C0;
    int group = lane >> 2, tg = lane & 3;
#pragma unroll
    for (int mi = 0; mi < 4; ++mi) {
#pragma unroll
        for (int n8 = 0; n8 < 4; ++n8) {
            int row = m0 + wm * 64 + mi * 16 + group;
            int col = n0 + wn * 32 + n8 * 8 + tg * 2;
            float bb0 = bias[col], bb1 = bias[col + 1];
            float y0 = fmaf((float)acc[mi][n8][0], s, bb0);
            float y1 = fmaf((float)acc[mi][n8][1], s, bb1);
            float y2 = fmaf((float)acc[mi][n8][2], s, bb0);
            float y3 = fmaf((float)acc[mi][n8][3], s, bb1);
            if (EPI == 0) {
                int h0, l0, h1, l1, h2, l2, h3, l3;
                q16(gelu_erf(y0), h0, l0); q16(gelu_erf(y1), h1, l1);
                q16(gelu_erf(y2), h2, l2); q16(gelu_erf(y3), h3, l3);
                *(int16_t*)&outH8[(size_t)row * N + col]       = (int16_t)((h0 & 0xFF) | ((h1 & 0xFF) << 8));
                *(int16_t*)&outH8[(size_t)(row + 8) * N + col] = (int16_t)((h2 & 0xFF) | ((h3 & 0xFF) << 8));
                *(int16_t*)&outL8[(size_t)row * N + col]       = (int16_t)((l0 & 0xFF) | ((l1 & 0xFF) << 8));
                *(int16_t*)&outL8[(size_t)(row + 8) * N + col] = (int16_t)((l2 & 0xFF) | ((l3 & 0xFF) << 8));
            } else {
                *(float2*)&outF[(size_t)row * N + col]       = make_float2(y0, y1);
                *(float2*)&outF[(size_t)(row + 8) * N + col] = make_float2(y2, y3);
            }
        }
    }
}

// ---- elementwise kernels ----
__device__ __forceinline__ float warpSum(float x) {
#pragma unroll
    for (int o = 16; o > 0; o >>= 1) x += __shfl_xor_sync(0xffffffffu, x, o);
    return x;
}
__device__ __forceinline__ float warpMax(float x) {
#pragma unroll
    for (int o = 16; o > 0; o >>= 1) x = fmaxf(x, __shfl_xor_sync(0xffffffffu, x, o));
    return x;
}

__global__ void absmean_partial(const float* w0, const float* w1, const float* w2, const float* w3) {
    const float* w = (blockIdx.y == 0) ? w0 : (blockIdx.y == 1) ? w1 : (blockIdx.y == 2) ? w2 : w3;
    const int chunk = (F_DIM * F_DIM) / 64;
    int base = blockIdx.x * chunk;
    float s = 0.f;
    for (int i = threadIdx.x; i < chunk; i += 256) s += fabsf(w[base + i]);
    __shared__ float red[8];
    s = warpSum(s);
    int wd = threadIdx.x >> 5, ln = threadIdx.x & 31;
    if (ln == 0) red[wd] = s;
    __syncthreads();
    if (wd == 0) {
        float v = (ln < 8) ? red[ln] : 0.f;
        v = warpSum(v);
        if (ln == 0) g_partials[blockIdx.y * 64 + blockIdx.x] = v;
    }
}

__global__ void quantize_ternary(const float* __restrict__ w, int8_t* __restrict__ kq, int slot) {
    float sum = 0.f;
#pragma unroll
    for (int i = 0; i < 64; i++) sum += g_partials[slot * 64 + i];
    float s = sum * (1.0f / (float)(F_DIM * F_DIM));
    if (blockIdx.x == 0 && threadIdx.x == 0) g_scale[slot] = s;
    float inv = 1.0f / (s + 1e-5f);
    int stride = gridDim.x * blockDim.x;
    for (int i = blockIdx.x * blockDim.x + threadIdx.x; i < F_DIM * F_DIM; i += stride) {
        float qv = rintf(fminf(fmaxf(w[i] * inv, -1.f), 1.f));
        kq[i] = (int8_t)(int)qv;
    }
}

__global__ void absmax_partial(const float* w0, const float* w1) {
    const float* w = blockIdx.y ? w1 : w0;
    const int chunk = (F2_DIM * F_DIM) / 64;
    int base = blockIdx.x * chunk;
    float m = 0.f;
    for (int i = threadIdx.x; i < chunk; i += 256) m = fmaxf(m, fabsf(w[base + i]));
    __shared__ float red[8];
    m = warpMax(m);
    int wd = threadIdx.x >> 5, ln = threadIdx.x & 31;
    if (ln == 0) red[wd] = m;
    __syncthreads();
    if (wd == 0) {
        float v = (ln < 8) ? red[ln] : 0.f;
        v = warpMax(v);
        if (ln == 0) g_pmax[blockIdx.y * 64 + blockIdx.x] = v;
    }
}

__global__ void quantize_w16(const float* __restrict__ w, int8_t* __restrict__ hi,
                             int8_t* __restrict__ lo, int slot, int n) {
    float m = 0.f;
#pragma unroll
    for (int i = 0; i < 64; i++) m = fmaxf(m, g_pmax[slot * 64 + i]);
    float Sw = 32512.f / m;
    if (blockIdx.x == 0 && threadIdx.x == 0) g_winv[slot] = m / 32512.f;
    int stride = gridDim.x * blockDim.x;
    for (int i = blockIdx.x * blockDim.x + threadIdx.x; i < n; i += stride) {
        int v = __float2int_rn(w[i] * Sw);
        v = v < -32512 ? -32512 : (v > 32512 ? 32512 : v);
        int l = (int)(int8_t)(v & 0xFF);
        lo[i] = (int8_t)l;
        hi[i] = (int8_t)((v - l) >> 8);
    }
}

__global__ void build_combined(const float* zb, const float* za, const float* ze,
                               const float* zm, const float* zs,
                               int8_t* __restrict__ ch, int8_t* __restrict__ cl) {
    int idx = blockIdx.x * 256 + threadIdx.x;
    int r = idx >> 9;
    int c4 = (idx & 511) * 4;
    const float* src; int off;
    if      (c4 < DB)                { src = zb; off = r * DB + c4; }
    else if (c4 < DB + DA)           { src = za; off = r * DA + (c4 - DB); }
    else if (c4 < DB + DA + DE)      { src = ze; off = r * DE + (c4 - DB - DA); }
    else if (c4 < DB + DA + DE + DM) { src = zm; off = r * DM + (c4 - DB - DA - DE); }
    else                             { src = zs; off = r * DS + (c4 - DB - DA - DE - DM); }
    float4 v = *reinterpret_cast<const float4*>(src + off);
    float vv[4] = {v.x, v.y, v.z, v.w};
    uint32_t ph = 0, pl = 0;
#pragma unroll
    for (int j = 0; j < 4; j++) {
        int h, l;
        q16(vv[j], h, l);
        ph |= (uint32_t)(h & 0xFF) << (j * 8);
        pl |= (uint32_t)(l & 0xFF) << (j * 8);
    }
    size_t o = (size_t)r * F_DIM + c4;
    *reinterpret_cast<uint32_t*>(&ch[o]) = ph;
    *reinterpret_cast<uint32_t*>(&cl[o]) = pl;
}

__global__ void fused_sig_ln(const float* __restrict__ g, const float* __restrict__ t,
                             const float* __restrict__ lg, const float* __restrict__ lb,
                             float* __restrict__ fused,
                             int8_t* __restrict__ fh, int8_t* __restrict__ fl) {
    int row = blockIdx.x;
    size_t base = (size_t)row * F_DIM;
    float v[8], s1 = 0.f, s2 = 0.f;
#pragma unroll
    for (int i = 0; i < 8; i++) {
        int c = i * 256 + threadIdx.x;
        float gg = g[base + c], tt = t[base + c];
        float f = tt / (1.0f + expf(-1.2f * gg));
        v[i] = f; s1 += f; s2 += f * f;
    }
    __shared__ float rs[8], rq[8];
    int wd = threadIdx.x >> 5, ln = threadIdx.x & 31;
    float a = warpSum(s1), b = warpSum(s2);
    if (ln == 0) { rs[wd] = a; rq[wd] = b; }
    __syncthreads();
    if (wd == 0) {
        float x = (ln < 8) ? rs[ln] : 0.f;
        float y = (ln < 8) ? rq[ln] : 0.f;
        x = warpSum(x); y = warpSum(y);
        if (ln == 0) { rs[0] = x; rq[0] = y; }
    }
    __syncthreads();
    float mean = rs[0] * (1.0f / F_DIM);
    float var = rq[0] * (1.0f / F_DIM) - mean * mean;
    float inv = rsqrtf(var + 1e-5f);
#pragma unroll
    for (int i = 0; i < 8; i++) {
        int c = i * 256 + threadIdx.x;
        float y = (v[i] - mean) * inv * lg[c] + lb[c];
        fused[base + c] = y;
        int h, l;
        q16(y, h, l);
        fh[base + c] = (int8_t)h;
        fl[base + c] = (int8_t)l;
    }
}

__global__ void final_ln(const float* __restrict__ fused, const float* __restrict__ mlp,
                         const float* __restrict__ lg, const float* __restrict__ lb,
                         float* __restrict__ out) {
    int row = blockIdx.x;
    size_t base = (size_t)row * F_DIM;
    float v[8], s1 = 0.f, s2 = 0.f;
#pragma unroll
    for (int i = 0; i < 8; i++) {
        int c = i * 256 + threadIdx.x;
        float f = fused[base + c] + mlp[base + c];
        v[i] = f; s1 += f; s2 += f * f;
    }
    __shared__ float rs[8], rq[8];
    int wd = threadIdx.x >> 5, ln = threadIdx.x & 31;
    float a = warpSum(s1), b = warpSum(s2);
    if (ln == 0) { rs[wd] = a; rq[wd] = b; }
    __syncthreads();
    if (wd == 0) {
        float x = (ln < 8) ? rs[ln] : 0.f;
        float y = (ln < 8) ? rq[ln] : 0.f;
        x = warpSum(x); y = warpSum(y);
        if (ln == 0) { rs[0] = x; rq[0] = y; }
    }
    __syncthreads();
    float mean = rs[0] * (1.0f / F_DIM);
    float var = rq[0] * (1.0f / F_DIM) - mean * mean;
    float inv = rsqrtf(var + 1e-5f);
#pragma unroll
    for (int i = 0; i < 8; i++) {
        int c = i * 256 + threadIdx.x;
        out[base + c] = (v[i] - mean) * inv * lg[c] + lb[c];
    }
}

// ---- launch ----
extern "C" void kernel_launch(void* const* d_in, const int* in_sizes, int n_in,
                              void* d_out, int out_size) {
    (void)in_sizes; (void)n_in; (void)out_size;
    const float* zb = (const float*)d_in[0];
    const float* za = (const float*)d_in[1];
    const float* ze = (const float*)d_in[2];
    const float* zm = (const float*)d_in[3];
    const float* zs = (const float*)d_in[4];
    const float* gate_w1 = (const float*)d_in[5];
    const float* gate_b1 = (const float*)d_in[6];
    const float* gate_w2 = (const float*)d_in[7];
    const float* gate_b2 = (const float*)d_in[8];
    const float* tr_w1 = (const float*)d_in[9];
    const float* tr_b1 = (const float*)d_in[10];
    const float* tr_w2 = (const float*)d_in[11];
    const float* tr_b2 = (const float*)d_in[12];
    const float* mlp_w1 = (const float*)d_in[13];
    const float* mlp_b1 = (const float*)d_in[14];
    const float* mlp_w2 = (const float*)d_in[15];
    const float* mlp_b2 = (const float*)d_in[16];
    const float* ln1_g = (const float*)d_in[17];
    const float* ln1_b = (const float*)d_in[18];
    const float* ln2_g = (const float*)d_in[19];
    const float* ln2_b = (const float*)d_in[20];
    float* out = (float*)d_out;

    int8_t *ch, *cl, *ah, *al, *wqb, *w1h, *w1l, *w2h, *w2l;
    float *fa, *fb, *fu, *scb, *winv;
    cudaGetSymbolAddress((void**)&ch,  g_c_hi);
    cudaGetSymbolAddress((void**)&cl,  g_c_lo);
    cudaGetSymbolAddress((void**)&ah,  g_a_hi);
    cudaGetSymbolAddress((void**)&al,  g_a_lo);
    cudaGetSymbolAddress((void**)&wqb, g_wq);
    cudaGetSymbolAddress((void**)&w1h, g_w1h);
    cudaGetSymbolAddress((void**)&w1l, g_w1l);
    cudaGetSymbolAddress((void**)&w2h, g_w2h);
    cudaGetSymbolAddress((void**)&w2l, g_w2l);
    cudaGetSymbolAddress((void**)&fa,  g_f32a);
    cudaGetSymbolAddress((void**)&fb,  g_f32b);
    cudaGetSymbolAddress((void**)&fu,  g_fused);
    cudaGetSymbolAddress((void**)&scb, g_scale);
    cudaGetSymbolAddress((void**)&winv, g_winv);
    int8_t* wq0 = wqb;
    int8_t* wq1 = wqb + (size_t)F_DIM * F_DIM;
    int8_t* wq2 = wqb + 2 * (size_t)F_DIM * F_DIM;
    int8_t* wq3 = wqb + 3 * (size_t)F_DIM * F_DIM;

    cudaFuncSetAttribute(gemm_i8<0>, cudaFuncAttributeMaxDynamicSharedMemorySize, GEMM_SMEM_DYN);
    cudaFuncSetAttribute(gemm_i8<1>, cudaFuncAttributeMaxDynamicSharedMemorySize, GEMM_SMEM_DYN);

    // Horner epilogue coefficients: acc already = p0*256 + p1 (+ p2)
    const float TC = 1.f / 4096.f;          // ternary: acc/Sx, times weight scale s
    const float MC = 256.f / 4096.f;        // mlp: 256*acc/Sx, times winv

    absmean_partial<<<dim3(64, 4), 256>>>(gate_w1, gate_w2, tr_w1, tr_w2);
    quantize_ternary<<<256, 256>>>(gate_w1, wq0, 0);
    quantize_ternary<<<256, 256>>>(gate_w2, wq1, 1);
    quantize_ternary<<<256, 256>>>(tr_w1, wq2, 2);
    quantize_ternary<<<256, 256>>>(tr_w2, wq3, 3);
    absmax_partial<<<dim3(64, 2), 256>>>(mlp_w1, mlp_w2);
    quantize_w16<<<512, 256>>>(mlp_w1, w1h, w1l, 0, F2_DIM * F_DIM);
    quantize_w16<<<512, 256>>>(mlp_w2, w2h, w2l, 1, F_DIM * F2_DIM);
    build_combined<<<(B_ROWS * 512) / 256, 256>>>(zb, za, ze, zm, zs, ch, cl);

    dim3 g2048(F_DIM / TILE_N, B_ROWS / TILE_M);   // (16, 64)
    dim3 g4096(F2_DIM / TILE_N, B_ROWS / TILE_M);  // (32, 64)

    // gate path: pass0 = hi, pass1 = lo (Horner x256 between)
    gemm_i8<0><<<g2048, 256, GEMM_SMEM_DYN>>>(ch, cl, nullptr, wq0, wq0, nullptr,
        2, F_DIM, F_DIM, TC, scb + 0, gate_b1, nullptr, ah, al);
    gemm_i8<1><<<g2048, 256, GEMM_SMEM_DYN>>>(ah, al, nullptr, wq1, wq1, nullptr,
        2, F_DIM, F_DIM, TC, scb + 1, gate_b2, fa, nullptr, nullptr);
    // transform path
    gemm_i8<0><<<g2048, 256, GEMM_SMEM_DYN>>>(ch, cl, nullptr, wq2, wq2, nullptr,
        2, F_DIM, F_DIM, TC, scb + 2, tr_b1, nullptr, ah, al);
    gemm_i8<1><<<g2048, 256, GEMM_SMEM_DYN>>>(ah, al, nullptr, wq3, wq3, nullptr,
        2, F_DIM, F_DIM, TC, scb + 3, tr_b2, fb, nullptr, nullptr);
    // sigmoid-gate fuse + ln1 (fused fp32 + int8 hi/lo reusing comb buffers)
    fused_sig_ln<<<B_ROWS, 256>>>(fa, fb, ln1_g, ln1_b, fu, ch, cl);
    // mlp1: passes (xh*wh)*256 + xh*wl + xl*wh
    gemm_i8<0><<<g4096, 256, GEMM_SMEM_DYN>>>(ch, ch, cl, w1h, w1l, w1h,
        3, F2_DIM, F_DIM, MC, winv + 0, mlp_b1, nullptr, ah, al);
    gemm_i8<1><<<g2048, 256, GEMM_SMEM_DYN>>>(ah, ah, al, w2h, w2l, w2h,
        3, F_DIM, F2_DIM, MC, winv + 1, mlp_b2, fa, nullptr, nullptr);
    // residual + ln2
    final_ln<<<B_ROWS, 256>>>(fu, fa, ln2_g, ln2_b, out);
}

// round 10
// speedup vs baseline: 4.4545x; 4.0970x over previous
#include <cuda_runtime.h>
#include <cuda_fp16.h>
#include <cstdint>
#include <math.h>

#define B_ROWS 8192
#define F_DIM  2048
#define F2_DIM 4096
#define DB 512
#define DA 256
#define DE 256
#define DM 512
#define DS 512

// ---- device scratch (allocation forbidden) ----
__device__ __align__(256) __half g_comb[B_ROWS * F_DIM];
__device__ __align__(256) __half g_act [B_ROWS * F2_DIM];
__device__ __align__(256) float g_f32a [B_ROWS * F_DIM];
__device__ __align__(256) float g_f32b [B_ROWS * F_DIM];
__device__ __align__(256) float g_fused[B_ROWS * F_DIM];
__device__ __align__(256) __half g_wq[4 * F_DIM * F_DIM];
__device__ __align__(256) __half g_w1h[F2_DIM * F_DIM];
__device__ __align__(256) __half g_w1l[F2_DIM * F_DIM];
__device__ __align__(256) __half g_w2h[F_DIM * F2_DIM];
__device__ __align__(256) __half g_w2l[F_DIM * F2_DIM];
__device__ float g_partials[4 * 64];
__device__ float g_scale[4];

// ---- helpers (baseline PTX only: cp.async, ldmatrix, mma.sync f16) ----
__device__ __forceinline__ uint32_t smem_u32(const void* p) {
    uint32_t a;
    asm("{ .reg .u64 t; cvta.to.shared.u64 t, %1; cvt.u32.u64 %0, t; }" : "=r"(a) : "l"(p));
    return a;
}
__device__ __forceinline__ uint32_t sw128(uint32_t x) { return x ^ ((x >> 3) & 0x70); }
__device__ __forceinline__ void cp16(uint32_t dst, const void* src) {
    asm volatile("cp.async.cg.shared.global [%0], [%1], 16;\n" :: "r"(dst), "l"(src) : "memory");
}
__device__ __forceinline__ void cp_commit() { asm volatile("cp.async.commit_group;\n" ::: "memory"); }
template <int N> __device__ __forceinline__ void cp_wait() {
    asm volatile("cp.async.wait_group %0;\n" :: "n"(N) : "memory");
}
__device__ __forceinline__ void ldsm4(uint32_t* r, uint32_t a) {
    asm volatile("ldmatrix.sync.aligned.m8n8.x4.shared.b16 {%0,%1,%2,%3}, [%4];"
        : "=r"(r[0]), "=r"(r[1]), "=r"(r[2]), "=r"(r[3]) : "r"(a));
}
__device__ __forceinline__ void mma_f16(float* c, const uint32_t* a, uint32_t b0, uint32_t b1) {
    asm volatile("mma.sync.aligned.m16n8k16.row.col.f32.f16.f16.f32 "
        "{%0,%1,%2,%3}, {%4,%5,%6,%7}, {%8,%9}, {%0,%1,%2,%3};"
        : "+f"(c[0]), "+f"(c[1]), "+f"(c[2]), "+f"(c[3])
        : "r"(a[0]), "r"(a[1]), "r"(a[2]), "r"(a[3]), "r"(b0), "r"(b1));
}
__device__ __forceinline__ float gelu_erf(float h) {
    return 0.5f * h * (1.0f + erff(h * 0.70710678f));
}
__device__ __forceinline__ uint32_t packh2(float a, float b) {
    __half2 v; v.x = __float2half_rn(a); v.y = __float2half_rn(b);
    return *reinterpret_cast<uint32_t*>(&v);
}

// ---- fp16 GEMM: C[M,N] = sum_p A[M,K] @ Bp[N,K]^T (Horner: acc*=hmul between passes) ----
#define TILE_M 128
#define TILE_N 128
#define TILE_K 64
#define STAGE_BYTES (TILE_M * 128 + TILE_N * 128)   // 32KB
#define STAGES 3
#define GEMM_SMEM_DYN (STAGES * STAGE_BYTES + 1024)

__device__ __forceinline__ void load_tiles(uint32_t sa, uint32_t sb,
        const __half* A, const __half* Bm, int m0, int n0, int k0, int K, int tid) {
    const char* ab = (const char*)(A + (size_t)m0 * K + k0);
    const char* bb = (const char*)(Bm + (size_t)n0 * K + k0);
    size_t rb = (size_t)K * 2;
#pragma unroll
    for (int i = 0; i < 4; i++) {
        int t = tid + i * 256, row = t >> 3, ch = t & 7;
        cp16(sa + sw128(row * 128 + ch * 16), ab + (size_t)row * rb + ch * 16);
    }
#pragma unroll
    for (int i = 0; i < 4; i++) {
        int t = tid + i * 256, row = t >> 3, ch = t & 7;
        cp16(sb + sw128(row * 128 + ch * 16), bb + (size_t)row * rb + ch * 16);
    }
}

template <int EPI>  // 0: gelu -> fp16; 1: fp32 out
__global__ void __launch_bounds__(256)
gemm_f16(const __half* A0, const __half* A1,
         const __half* B0, const __half* B1,
         int n_pass, int N, int K, float hmul,
         const float* scale_ptr, const float* __restrict__ bias,
         float* outF, __half* outH) {
    extern __shared__ char smem[];
    uint32_t sbase = (smem_u32(smem) + 1023) & ~1023u;
    int tid = threadIdx.x, wid = tid >> 5, lane = tid & 31;
    int n0 = blockIdx.x * TILE_N, m0 = blockIdx.y * TILE_M;
    int wm = wid & 1, wn = wid >> 1;
    const __half* Al[2] = {A0, A1};
    const __half* Bl[2] = {B0, B1};
    const int KT = K / TILE_K;
    const int iters = n_pass * KT;

    for (int p = 0; p < 2 && p < iters; ++p) {
        int sp = p / KT, kk = (p % KT) * TILE_K;
        uint32_t st = sbase + p * STAGE_BYTES;
        load_tiles(st, st + TILE_M * 128, Al[sp], Bl[sp], m0, n0, kk, K, tid);
        cp_commit();
    }

    float acc[4][4][4];
#pragma unroll
    for (int i = 0; i < 4; i++)
#pragma unroll
        for (int j = 0; j < 4; j++)
#pragma unroll
            for (int k = 0; k < 4; k++) acc[i][j][k] = 0.f;

    int q = lane >> 3, r = lane & 7;
    int aRow = wm * 64 + r + (q & 1) * 8;
    int aCol = (q >> 1) * 16;
    int bRow = wn * 32 + r + (q >> 1) * 8;
    int bCol = (q & 1) * 16;

    for (int it = 0; it < iters; ++it) {
        if (it == KT) {   // Horner: pass0 (scaled weight residual) down-weighted
#pragma unroll
            for (int i = 0; i < 4; i++)
#pragma unroll
                for (int j = 0; j < 4; j++)
#pragma unroll
                    for (int k = 0; k < 4; k++) acc[i][j][k] *= hmul;
        }
        cp_wait<1>();
        __syncthreads();
        if (it + 2 < iters) {
            int nit = it + 2, sp = nit / KT, kk = (nit % KT) * TILE_K;
            uint32_t st = sbase + (nit % STAGES) * STAGE_BYTES;
            load_tiles(st, st + TILE_M * 128, Al[sp], Bl[sp], m0, n0, kk, K, tid);
        }
        cp_commit();
        uint32_t sA = sbase + (it % STAGES) * STAGE_BYTES;
        uint32_t sB = sA + TILE_M * 128;
#pragma unroll
        for (int ks = 0; ks < 4; ++ks) {
            uint32_t a[4][4], b[2][4];
#pragma unroll
            for (int mi = 0; mi < 4; ++mi)
                ldsm4(a[mi], sA + sw128((aRow + mi * 16) * 128 + aCol + ks * 32));
#pragma unroll
            for (int nj = 0; nj < 2; ++nj)
                ldsm4(b[nj], sB + sw128((bRow + nj * 16) * 128 + bCol + ks * 32));
#pragma unroll
            for (int mi = 0; mi < 4; ++mi)
#pragma unroll
                for (int n8 = 0; n8 < 4; ++n8)
                    mma_f16(acc[mi][n8], a[mi],
                            b[n8 >> 1][(n8 & 1) * 2], b[n8 >> 1][(n8 & 1) * 2 + 1]);
        }
    }

    float sc = scale_ptr ? *scale_ptr : 1.0f;
    int group = lane >> 2, tg = lane & 3;
#pragma unroll
    for (int mi = 0; mi < 4; ++mi) {
#pragma unroll
        for (int n8 = 0; n8 < 4; ++n8) {
            int row = m0 + wm * 64 + mi * 16 + group;
            int col = n0 + wn * 32 + n8 * 8 + tg * 2;
            float bb0 = bias[col], bb1 = bias[col + 1];
            float y0 = fmaf(sc, acc[mi][n8][0], bb0);
            float y1 = fmaf(sc, acc[mi][n8][1], bb1);
            float y2 = fmaf(sc, acc[mi][n8][2], bb0);
            float y3 = fmaf(sc, acc[mi][n8][3], bb1);
            if (EPI == 0) {
                *(uint32_t*)&outH[(size_t)row * N + col]       = packh2(gelu_erf(y0), gelu_erf(y1));
                *(uint32_t*)&outH[(size_t)(row + 8) * N + col] = packh2(gelu_erf(y2), gelu_erf(y3));
            } else {
                *(float2*)&outF[(size_t)row * N + col]       = make_float2(y0, y1);
                *(float2*)&outF[(size_t)(row + 8) * N + col] = make_float2(y2, y3);
            }
        }
    }
}

// ---- elementwise kernels ----
__device__ __forceinline__ float warpSum(float x) {
#pragma unroll
    for (int o = 16; o > 0; o >>= 1) x += __shfl_xor_sync(0xffffffffu, x, o);
    return x;
}

__global__ void absmean_partial(const float* w0, const float* w1, const float* w2, const float* w3) {
    const float* w = (blockIdx.y == 0) ? w0 : (blockIdx.y == 1) ? w1 : (blockIdx.y == 2) ? w2 : w3;
    const int chunk = (F_DIM * F_DIM) / 64;
    int base = blockIdx.x * chunk;
    float s = 0.f;
    for (int i = threadIdx.x; i < chunk; i += 256) s += fabsf(w[base + i]);
    __shared__ float red[8];
    s = warpSum(s);
    int wd = threadIdx.x >> 5, ln = threadIdx.x & 31;
    if (ln == 0) red[wd] = s;
    __syncthreads();
    if (wd == 0) {
        float v = (ln < 8) ? red[ln] : 0.f;
        v = warpSum(v);
        if (ln == 0) g_partials[blockIdx.y * 64 + blockIdx.x] = v;
    }
}

__global__ void quantize_ternary(const float* __restrict__ w, __half* __restrict__ kq, int slot) {
    float sum = 0.f;
#pragma unroll
    for (int i = 0; i < 64; i++) sum += g_partials[slot * 64 + i];
    float s = sum * (1.0f / (float)(F_DIM * F_DIM));
    if (blockIdx.x == 0 && threadIdx.x == 0) g_scale[slot] = s;
    float inv = 1.0f / (s + 1e-5f);
    int stride = gridDim.x * blockDim.x;
    for (int i = blockIdx.x * blockDim.x + threadIdx.x; i < F_DIM * F_DIM; i += stride) {
        float qv = rintf(fminf(fmaxf(w[i] * inv, -1.f), 1.f));
        kq[i] = __float2half_rn(qv);
    }
}

// wh = fp16(w); wls = fp16((w - wh) * 2048)  (Horner residual, pre-scaled)
__global__ void split_w(const float* __restrict__ w, __half* __restrict__ hi,
                        __half* __restrict__ lols, int n) {
    int stride = gridDim.x * blockDim.x;
    for (int i = blockIdx.x * blockDim.x + threadIdx.x; i < n; i += stride) {
        float v = w[i];
        __half h = __float2half_rn(v);
        hi[i] = h;
        lols[i] = __float2half_rn((v - __half2float(h)) * 2048.f);
    }
}

__global__ void build_combined(const float* zb, const float* za, const float* ze,
                               const float* zm, const float* zs, __half* __restrict__ ch) {
    int idx = blockIdx.x * 256 + threadIdx.x;
    int r = idx >> 9;
    int c4 = (idx & 511) * 4;
    const float* src; int off;
    if      (c4 < DB)                { src = zb; off = r * DB + c4; }
    else if (c4 < DB + DA)           { src = za; off = r * DA + (c4 - DB); }
    else if (c4 < DB + DA + DE)      { src = ze; off = r * DE + (c4 - DB - DA); }
    else if (c4 < DB + DA + DE + DM) { src = zm; off = r * DM + (c4 - DB - DA - DE); }
    else                             { src = zs; off = r * DS + (c4 - DB - DA - DE - DM); }
    float4 v = *reinterpret_cast<const float4*>(src + off);
    uint2 u;
    u.x = packh2(v.x, v.y);
    u.y = packh2(v.z, v.w);
    *reinterpret_cast<uint2*>(&ch[(size_t)r * F_DIM + c4]) = u;
}

__global__ void fused_sig_ln(const float* __restrict__ g, const float* __restrict__ t,
                             const float* __restrict__ lg, const float* __restrict__ lb,
                             float* __restrict__ fused, __half* __restrict__ fh) {
    int row = blockIdx.x;
    size_t base = (size_t)row * F_DIM;
    float v[8], s1 = 0.f, s2 = 0.f;
#pragma unroll
    for (int i = 0; i < 8; i++) {
        int c = i * 256 + threadIdx.x;
        float gg = g[base + c], tt = t[base + c];
        float f = tt / (1.0f + expf(-1.2f * gg));
        v[i] = f; s1 += f; s2 += f * f;
    }
    __shared__ float rs[8], rq[8];
    int wd = threadIdx.x >> 5, ln = threadIdx.x & 31;
    float a = warpSum(s1), b = warpSum(s2);
    if (ln == 0) { rs[wd] = a; rq[wd] = b; }
    __syncthreads();
    if (wd == 0) {
        float x = (ln < 8) ? rs[ln] : 0.f;
        float y = (ln < 8) ? rq[ln] : 0.f;
        x = warpSum(x); y = warpSum(y);
        if (ln == 0) { rs[0] = x; rq[0] = y; }
    }
    __syncthreads();
    float mean = rs[0] * (1.0f / F_DIM);
    float var = rq[0] * (1.0f / F_DIM) - mean * mean;
    float inv = rsqrtf(var + 1e-5f);
#pragma unroll
    for (int i = 0; i < 8; i++) {
        int c = i * 256 + threadIdx.x;
        float y = (v[i] - mean) * inv * lg[c] + lb[c];
        fused[base + c] = y;
        fh[base + c] = __float2half_rn(y);
    }
}

__global__ void final_ln(const float* __restrict__ fused, const float* __restrict__ mlp,
                         const float* __restrict__ lg, const float* __restrict__ lb,
                         float* __restrict__ out) {
    int row = blockIdx.x;
    size_t base = (size_t)row * F_DIM;
    float v[8], s1 = 0.f, s2 = 0.f;
#pragma unroll
    for (int i = 0; i < 8; i++) {
        int c = i * 256 + threadIdx.x;
        float f = fused[base + c] + mlp[base + c];
        v[i] = f; s1 += f; s2 += f * f;
    }
    __shared__ float rs[8], rq[8];
    int wd = threadIdx.x >> 5, ln = threadIdx.x & 31;
    float a = warpSum(s1), b = warpSum(s2);
    if (ln == 0) { rs[wd] = a; rq[wd] = b; }
    __syncthreads();
    if (wd == 0) {
        float x = (ln < 8) ? rs[ln] : 0.f;
        float y = (ln < 8) ? rq[ln] : 0.f;
        x = warpSum(x); y = warpSum(y);
        if (ln == 0) { rs[0] = x; rq[0] = y; }
    }
    __syncthreads();
    float mean = rs[0] * (1.0f / F_DIM);
    float var = rq[0] * (1.0f / F_DIM) - mean * mean;
    float inv = rsqrtf(var + 1e-5f);
#pragma unroll
    for (int i = 0; i < 8; i++) {
        int c = i * 256 + threadIdx.x;
        out[base + c] = (v[i] - mean) * inv * lg[c] + lb[c];
    }
}

// ---- launch ----
extern "C" void kernel_launch(void* const* d_in, const int* in_sizes, int n_in,
                              void* d_out, int out_size) {
    (void)in_sizes; (void)n_in; (void)out_size;
    const float* zb = (const float*)d_in[0];
    const float* za = (const float*)d_in[1];
    const float* ze = (const float*)d_in[2];
    const float* zm = (const float*)d_in[3];
    const float* zs = (const float*)d_in[4];
    const float* gate_w1 = (const float*)d_in[5];
    const float* gate_b1 = (const float*)d_in[6];
    const float* gate_w2 = (const float*)d_in[7];
    const float* gate_b2 = (const float*)d_in[8];
    const float* tr_w1 = (const float*)d_in[9];
    const float* tr_b1 = (const float*)d_in[10];
    const float* tr_w2 = (const float*)d_in[11];
    const float* tr_b2 = (const float*)d_in[12];
    const float* mlp_w1 = (const float*)d_in[13];
    const float* mlp_b1 = (const float*)d_in[14];
    const float* mlp_w2 = (const float*)d_in[15];
    const float* mlp_b2 = (const float*)d_in[16];
    const float* ln1_g = (const float*)d_in[17];
    const float* ln1_b = (const float*)d_in[18];
    const float* ln2_g = (const float*)d_in[19];
    const float* ln2_b = (const float*)d_in[20];
    float* out = (float*)d_out;

    __half *ch, *ah, *wqb, *w1h, *w1l, *w2h, *w2l;
    float *fa, *fb, *fu, *scb;
    cudaGetSymbolAddress((void**)&ch,  g_comb);
    cudaGetSymbolAddress((void**)&ah,  g_act);
    cudaGetSymbolAddress((void**)&wqb, g_wq);
    cudaGetSymbolAddress((void**)&w1h, g_w1h);
    cudaGetSymbolAddress((void**)&w1l, g_w1l);
    cudaGetSymbolAddress((void**)&w2h, g_w2h);
    cudaGetSymbolAddress((void**)&w2l, g_w2l);
    cudaGetSymbolAddress((void**)&fa,  g_f32a);
    cudaGetSymbolAddress((void**)&fb,  g_f32b);
    cudaGetSymbolAddress((void**)&fu,  g_fused);
    cudaGetSymbolAddress((void**)&scb, g_scale);
    __half* wq0 = wqb;
    __half* wq1 = wqb + (size_t)F_DIM * F_DIM;
    __half* wq2 = wqb + 2 * (size_t)F_DIM * F_DIM;
    __half* wq3 = wqb + 3 * (size_t)F_DIM * F_DIM;

    cudaFuncSetAttribute(gemm_f16<0>, cudaFuncAttributeMaxDynamicSharedMemorySize, GEMM_SMEM_DYN);
    cudaFuncSetAttribute(gemm_f16<1>, cudaFuncAttributeMaxDynamicSharedMemorySize, GEMM_SMEM_DYN);

    const float HMUL = 1.f / 2048.f;   // undo the x2048 pre-scale of the weight residual

    // weight prep
    absmean_partial<<<dim3(64, 4), 256>>>(gate_w1, gate_w2, tr_w1, tr_w2);
    quantize_ternary<<<256, 256>>>(gate_w1, wq0, 0);
    quantize_ternary<<<256, 256>>>(gate_w2, wq1, 1);
    quantize_ternary<<<256, 256>>>(tr_w1, wq2, 2);
    quantize_ternary<<<256, 256>>>(tr_w2, wq3, 3);
    split_w<<<2048, 256>>>(mlp_w1, w1h, w1l, F2_DIM * F_DIM);
    split_w<<<2048, 256>>>(mlp_w2, w2h, w2l, F_DIM * F2_DIM);
    build_combined<<<(B_ROWS * 512) / 256, 256>>>(zb, za, ze, zm, zs, ch);

    dim3 g2048(F_DIM / TILE_N, B_ROWS / TILE_M);   // (16, 64)
    dim3 g4096(F2_DIM / TILE_N, B_ROWS / TILE_M);  // (32, 64)

    // gate path (single fp16 pass; ternary weights exact)
    gemm_f16<0><<<g2048, 256, GEMM_SMEM_DYN>>>(ch, ch, wq0, wq0,
        1, F_DIM, F_DIM, 1.f, scb + 0, gate_b1, nullptr, ah);
    gemm_f16<1><<<g2048, 256, GEMM_SMEM_DYN>>>(ah, ah, wq1, wq1,
        1, F_DIM, F_DIM, 1.f, scb + 1, gate_b2, fa, nullptr);
    // transform path
    gemm_f16<0><<<g2048, 256, GEMM_SMEM_DYN>>>(ch, ch, wq2, wq2,
        1, F_DIM, F_DIM, 1.f, scb + 2, tr_b1, nullptr, ah);
    gemm_f16<1><<<g2048, 256, GEMM_SMEM_DYN>>>(ah, ah, wq3, wq3,
        1, F_DIM, F_DIM, 1.f, scb + 3, tr_b2, fb, nullptr);
    // sigmoid-gate fuse + ln1 (fused fp32 + fp16 copy reusing comb buffer)
    fused_sig_ln<<<B_ROWS, 256>>>(fa, fb, ln1_g, ln1_b, fu, ch);
    // mlp: 2 Horner passes (residual*2048 first, then *1/2048, then main)
    gemm_f16<0><<<g4096, 256, GEMM_SMEM_DYN>>>(ch, ch, w1l, w1h,
        2, F2_DIM, F_DIM, HMUL, nullptr, mlp_b1, nullptr, ah);
    gemm_f16<1><<<g2048, 256, GEMM_SMEM_DYN>>>(ah, ah, w2l, w2h,
        2, F_DIM, F2_DIM, HMUL, nullptr, mlp_b2, fa, nullptr);
    // residual + ln2
    final_ln<<<B_ROWS, 256>>>(fu, fa, ln2_g, ln2_b, out);
}

// round 11
// speedup vs baseline: 6.2574x; 1.4047x over previous
#include <cuda_runtime.h>
#include <cuda_fp16.h>
#include <cstdint>
#include <math.h>

#define B_ROWS 8192
#define F_DIM  2048
#define F2_DIM 4096
#define DB 512
#define DA 256
#define DE 256
#define DM 512
#define DS 512

// ---- device scratch (allocation forbidden) ----
__device__ __align__(256) __half g_comb[B_ROWS * F_DIM];
__device__ __align__(256) __half g_act [B_ROWS * F2_DIM];
__device__ __align__(256) float g_f32a [B_ROWS * F_DIM];
__device__ __align__(256) float g_f32b [B_ROWS * F_DIM];
__device__ __align__(256) float g_fused[B_ROWS * F_DIM];
__device__ __align__(256) __half g_wq[4 * F_DIM * F_DIM];
__device__ __align__(256) __half g_w1h[F2_DIM * F_DIM];
__device__ __align__(256) __half g_w2h[F_DIM * F2_DIM];
__device__ float g_partials[4 * 64];
__device__ float g_scale[4];

// ---- helpers (baseline PTX only: cp.async, ldmatrix, mma.sync f16) ----
__device__ __forceinline__ uint32_t smem_u32(const void* p) {
    uint32_t a;
    asm("{ .reg .u64 t; cvta.to.shared.u64 t, %1; cvt.u32.u64 %0, t; }" : "=r"(a) : "l"(p));
    return a;
}
__device__ __forceinline__ uint32_t sw128(uint32_t x) { return x ^ ((x >> 3) & 0x70); }
__device__ __forceinline__ void cp16(uint32_t dst, const void* src) {
    asm volatile("cp.async.cg.shared.global [%0], [%1], 16;\n" :: "r"(dst), "l"(src) : "memory");
}
__device__ __forceinline__ void cp_commit() { asm volatile("cp.async.commit_group;\n" ::: "memory"); }
template <int N> __device__ __forceinline__ void cp_wait() {
    asm volatile("cp.async.wait_group %0;\n" :: "n"(N) : "memory");
}
__device__ __forceinline__ void ldsm4(uint32_t* r, uint32_t a) {
    asm volatile("ldmatrix.sync.aligned.m8n8.x4.shared.b16 {%0,%1,%2,%3}, [%4];"
        : "=r"(r[0]), "=r"(r[1]), "=r"(r[2]), "=r"(r[3]) : "r"(a));
}
__device__ __forceinline__ void mma_f16(float* c, const uint32_t* a, uint32_t b0, uint32_t b1) {
    asm volatile("mma.sync.aligned.m16n8k16.row.col.f32.f16.f16.f32 "
        "{%0,%1,%2,%3}, {%4,%5,%6,%7}, {%8,%9}, {%0,%1,%2,%3};"
        : "+f"(c[0]), "+f"(c[1]), "+f"(c[2]), "+f"(c[3])
        : "r"(a[0]), "r"(a[1]), "r"(a[2]), "r"(a[3]), "r"(b0), "r"(b1));
}
__device__ __forceinline__ float gelu_erf(float h) {
    return 0.5f * h * (1.0f + erff(h * 0.70710678f));
}
__device__ __forceinline__ uint32_t packh2(float a, float b) {
    __half2 v; v.x = __float2half_rn(a); v.y = __float2half_rn(b);
    return *reinterpret_cast<uint32_t*>(&v);
}

// ---- fp16 GEMM: C[M,N] = sum_p A[M,K] @ Bp[N,K]^T (Horner: acc*=hmul between passes) ----
#define TILE_M 128
#define TILE_N 128
#define TILE_K 64
#define STAGE_BYTES (TILE_M * 128 + TILE_N * 128)   // 32KB
#define STAGES 3
#define GEMM_SMEM_DYN (STAGES * STAGE_BYTES + 1024)

__device__ __forceinline__ void load_tiles(uint32_t sa, uint32_t sb,
        const __half* A, const __half* Bm, int m0, int n0, int k0, int K, int tid) {
    const char* ab = (const char*)(A + (size_t)m0 * K + k0);
    const char* bb = (const char*)(Bm + (size_t)n0 * K + k0);
    size_t rb = (size_t)K * 2;
#pragma unroll
    for (int i = 0; i < 4; i++) {
        int t = tid + i * 256, row = t >> 3, ch = t & 7;
        cp16(sa + sw128(row * 128 + ch * 16), ab + (size_t)row * rb + ch * 16);
    }
#pragma unroll
    for (int i = 0; i < 4; i++) {
        int t = tid + i * 256, row = t >> 3, ch = t & 7;
        cp16(sb + sw128(row * 128 + ch * 16), bb + (size_t)row * rb + ch * 16);
    }
}

template <int EPI>  // 0: gelu -> fp16; 1: fp32 out
__global__ void __launch_bounds__(256)
gemm_f16(const __half* A0, const __half* A1,
         const __half* B0, const __half* B1,
         int n_pass, int N, int K, float hmul,
         const float* scale_ptr, const float* __restrict__ bias,
         float* outF, __half* outH) {
    extern __shared__ char smem[];
    uint32_t sbase = (smem_u32(smem) + 1023) & ~1023u;
    int tid = threadIdx.x, wid = tid >> 5, lane = tid & 31;
    int n0 = blockIdx.x * TILE_N, m0 = blockIdx.y * TILE_M;
    int wm = wid & 1, wn = wid >> 1;
    const __half* Al[2] = {A0, A1};
    const __half* Bl[2] = {B0, B1};
    const int KT = K / TILE_K;
    const int iters = n_pass * KT;

    for (int p = 0; p < 2 && p < iters; ++p) {
        int sp = p / KT, kk = (p % KT) * TILE_K;
        uint32_t st = sbase + p * STAGE_BYTES;
        load_tiles(st, st + TILE_M * 128, Al[sp], Bl[sp], m0, n0, kk, K, tid);
        cp_commit();
    }

    float acc[4][4][4];
#pragma unroll
    for (int i = 0; i < 4; i++)
#pragma unroll
        for (int j = 0; j < 4; j++)
#pragma unroll
            for (int k = 0; k < 4; k++) acc[i][j][k] = 0.f;

    int q = lane >> 3, r = lane & 7;
    int aRow = wm * 64 + r + (q & 1) * 8;
    int aCol = (q >> 1) * 16;
    int bRow = wn * 32 + r + (q >> 1) * 8;
    int bCol = (q & 1) * 16;

    for (int it = 0; it < iters; ++it) {
        if (it == KT) {   // Horner boundary (unused when n_pass==1)
#pragma unroll
            for (int i = 0; i < 4; i++)
#pragma unroll
                for (int j = 0; j < 4; j++)
#pragma unroll
                    for (int k = 0; k < 4; k++) acc[i][j][k] *= hmul;
        }
        cp_wait<1>();
        __syncthreads();
        if (it + 2 < iters) {
            int nit = it + 2, sp = nit / KT, kk = (nit % KT) * TILE_K;
            uint32_t st = sbase + (nit % STAGES) * STAGE_BYTES;
            load_tiles(st, st + TILE_M * 128, Al[sp], Bl[sp], m0, n0, kk, K, tid);
        }
        cp_commit();
        uint32_t sA = sbase + (it % STAGES) * STAGE_BYTES;
        uint32_t sB = sA + TILE_M * 128;
#pragma unroll
        for (int ks = 0; ks < 4; ++ks) {
            uint32_t a[4][4], b[2][4];
#pragma unroll
            for (int mi = 0; mi < 4; ++mi)
                ldsm4(a[mi], sA + sw128((aRow + mi * 16) * 128 + aCol + ks * 32));
#pragma unroll
            for (int nj = 0; nj < 2; ++nj)
                ldsm4(b[nj], sB + sw128((bRow + nj * 16) * 128 + bCol + ks * 32));
#pragma unroll
            for (int mi = 0; mi < 4; ++mi)
#pragma unroll
                for (int n8 = 0; n8 < 4; ++n8)
                    mma_f16(acc[mi][n8], a[mi],
                            b[n8 >> 1][(n8 & 1) * 2], b[n8 >> 1][(n8 & 1) * 2 + 1]);
        }
    }

    float sc = scale_ptr ? *scale_ptr : 1.0f;
    int group = lane >> 2, tg = lane & 3;
#pragma unroll
    for (int mi = 0; mi < 4; ++mi) {
#pragma unroll
        for (int n8 = 0; n8 < 4; ++n8) {
            int row = m0 + wm * 64 + mi * 16 + group;
            int col = n0 + wn * 32 + n8 * 8 + tg * 2;
            float bb0 = bias[col], bb1 = bias[col + 1];
            float y0 = fmaf(sc, acc[mi][n8][0], bb0);
            float y1 = fmaf(sc, acc[mi][n8][1], bb1);
            float y2 = fmaf(sc, acc[mi][n8][2], bb0);
            float y3 = fmaf(sc, acc[mi][n8][3], bb1);
            if (EPI == 0) {
                *(uint32_t*)&outH[(size_t)row * N + col]       = packh2(gelu_erf(y0), gelu_erf(y1));
                *(uint32_t*)&outH[(size_t)(row + 8) * N + col] = packh2(gelu_erf(y2), gelu_erf(y3));
            } else {
                *(float2*)&outF[(size_t)row * N + col]       = make_float2(y0, y1);
                *(float2*)&outF[(size_t)(row + 8) * N + col] = make_float2(y2, y3);
            }
        }
    }
}

// ---- elementwise kernels ----
__device__ __forceinline__ float warpSum(float x) {
#pragma unroll
    for (int o = 16; o > 0; o >>= 1) x += __shfl_xor_sync(0xffffffffu, x, o);
    return x;
}

__global__ void absmean_partial(const float* w0, const float* w1, const float* w2, const float* w3) {
    const float* w = (blockIdx.y == 0) ? w0 : (blockIdx.y == 1) ? w1 : (blockIdx.y == 2) ? w2 : w3;
    const int chunk = (F_DIM * F_DIM) / 64;
    int base = blockIdx.x * chunk;
    float s = 0.f;
    for (int i = threadIdx.x; i < chunk; i += 256) s += fabsf(w[base + i]);
    __shared__ float red[8];
    s = warpSum(s);
    int wd = threadIdx.x >> 5, ln = threadIdx.x & 31;
    if (ln == 0) red[wd] = s;
    __syncthreads();
    if (wd == 0) {
        float v = (ln < 8) ? red[ln] : 0.f;
        v = warpSum(v);
        if (ln == 0) g_partials[blockIdx.y * 64 + blockIdx.x] = v;
    }
}

__global__ void quantize_ternary(const float* w0, const float* w1, const float* w2, const float* w3,
                                 __half* __restrict__ kq) {
    int slot = blockIdx.y;
    const float* w = (slot == 0) ? w0 : (slot == 1) ? w1 : (slot == 2) ? w2 : w3;
    __half* dst = kq + (size_t)slot * F_DIM * F_DIM;
    float sum = 0.f;
#pragma unroll
    for (int i = 0; i < 64; i++) sum += g_partials[slot * 64 + i];
    float s = sum * (1.0f / (float)(F_DIM * F_DIM));
    if (blockIdx.x == 0 && threadIdx.x == 0) g_scale[slot] = s;
    float inv = 1.0f / (s + 1e-5f);
    int stride = gridDim.x * blockDim.x;
    for (int i = blockIdx.x * blockDim.x + threadIdx.x; i < F_DIM * F_DIM; i += stride) {
        float qv = rintf(fminf(fmaxf(w[i] * inv, -1.f), 1.f));
        dst[i] = __float2half_rn(qv);
    }
}

__global__ void convert_w(const float* __restrict__ w, __half* __restrict__ hi, int n) {
    int stride = gridDim.x * blockDim.x;
    for (int i = blockIdx.x * blockDim.x + threadIdx.x; i < n; i += stride)
        hi[i] = __float2half_rn(w[i]);
}

__global__ void build_combined(const float* zb, const float* za, const float* ze,
                               const float* zm, const float* zs, __half* __restrict__ ch) {
    int idx = blockIdx.x * 256 + threadIdx.x;
    int r = idx >> 9;
    int c4 = (idx & 511) * 4;
    const float* src; int off;
    if      (c4 < DB)                { src = zb; off = r * DB + c4; }
    else if (c4 < DB + DA)           { src = za; off = r * DA + (c4 - DB); }
    else if (c4 < DB + DA + DE)      { src = ze; off = r * DE + (c4 - DB - DA); }
    else if (c4 < DB + DA + DE + DM) { src = zm; off = r * DM + (c4 - DB - DA - DE); }
    else                             { src = zs; off = r * DS + (c4 - DB - DA - DE - DM); }
    float4 v = *reinterpret_cast<const float4*>(src + off);
    uint2 u;
    u.x = packh2(v.x, v.y);
    u.y = packh2(v.z, v.w);
    *reinterpret_cast<uint2*>(&ch[(size_t)r * F_DIM + c4]) = u;
}

__global__ void fused_sig_ln(const float* __restrict__ g, const float* __restrict__ t,
                             const float* __restrict__ lg, const float* __restrict__ lb,
                             float* __restrict__ fused, __half* __restrict__ fh) {
    int row = blockIdx.x;
    size_t base = (size_t)row * F_DIM;
    float v[8], s1 = 0.f, s2 = 0.f;
#pragma unroll
    for (int i = 0; i < 8; i++) {
        int c = i * 256 + threadIdx.x;
        float gg = g[base + c], tt = t[base + c];
        float f = tt / (1.0f + expf(-1.2f * gg));
        v[i] = f; s1 += f; s2 += f * f;
    }
    __shared__ float rs[8], rq[8];
    int wd = threadIdx.x >> 5, ln = threadIdx.x & 31;
    float a = warpSum(s1), b = warpSum(s2);
    if (ln == 0) { rs[wd] = a; rq[wd] = b; }
    __syncthreads();
    if (wd == 0) {
        float x = (ln < 8) ? rs[ln] : 0.f;
        float y = (ln < 8) ? rq[ln] : 0.f;
        x = warpSum(x); y = warpSum(y);
        if (ln == 0) { rs[0] = x; rq[0] = y; }
    }
    __syncthreads();
    float mean = rs[0] * (1.0f / F_DIM);
    float var = rq[0] * (1.0f / F_DIM) - mean * mean;
    float inv = rsqrtf(var + 1e-5f);
#pragma unroll
    for (int i = 0; i < 8; i++) {
        int c = i * 256 + threadIdx.x;
        float y = (v[i] - mean) * inv * lg[c] + lb[c];
        fused[base + c] = y;
        fh[base + c] = __float2half_rn(y);
    }
}

__global__ void final_ln(const float* __restrict__ fused, const float* __restrict__ mlp,
                         const float* __restrict__ lg, const float* __restrict__ lb,
                         float* __restrict__ out) {
    int row = blockIdx.x;
    size_t base = (size_t)row * F_DIM;
    float v[8], s1 = 0.f, s2 = 0.f;
#pragma unroll
    for (int i = 0; i < 8; i++) {
        int c = i * 256 + threadIdx.x;
        float f = fused[base + c] + mlp[base + c];
        v[i] = f; s1 += f; s2 += f * f;
    }
    __shared__ float rs[8], rq[8];
    int wd = threadIdx.x >> 5, ln = threadIdx.x & 31;
    float a = warpSum(s1), b = warpSum(s2);
    if (ln == 0) { rs[wd] = a; rq[wd] = b; }
    __syncthreads();
    if (wd == 0) {
        float x = (ln < 8) ? rs[ln] : 0.f;
        float y = (ln < 8) ? rq[ln] : 0.f;
        x = warpSum(x); y = warpSum(y);
        if (ln == 0) { rs[0] = x; rq[0] = y; }
    }
    __syncthreads();
    float mean = rs[0] * (1.0f / F_DIM);
    float var = rq[0] * (1.0f / F_DIM) - mean * mean;
    float inv = rsqrtf(var + 1e-5f);
#pragma unroll
    for (int i = 0; i < 8; i++) {
        int c = i * 256 + threadIdx.x;
        out[base + c] = (v[i] - mean) * inv * lg[c] + lb[c];
    }
}

// ---- launch ----
extern "C" void kernel_launch(void* const* d_in, const int* in_sizes, int n_in,
                              void* d_out, int out_size) {
    (void)in_sizes; (void)n_in; (void)out_size;
    const float* zb = (const float*)d_in[0];
    const float* za = (const float*)d_in[1];
    const float* ze = (const float*)d_in[2];
    const float* zm = (const float*)d_in[3];
    const float* zs = (const float*)d_in[4];
    const float* gate_w1 = (const float*)d_in[5];
    const float* gate_b1 = (const float*)d_in[6];
    const float* gate_w2 = (const float*)d_in[7];
    const float* gate_b2 = (const float*)d_in[8];
    const float* tr_w1 = (const float*)d_in[9];
    const float* tr_b1 = (const float*)d_in[10];
    const float* tr_w2 = (const float*)d_in[11];
    const float* tr_b2 = (const float*)d_in[12];
    const float* mlp_w1 = (const float*)d_in[13];
    const float* mlp_b1 = (const float*)d_in[14];
    const float* mlp_w2 = (const float*)d_in[15];
    const float* mlp_b2 = (const float*)d_in[16];
    const float* ln1_g = (const float*)d_in[17];
    const float* ln1_b = (const float*)d_in[18];
    const float* ln2_g = (const float*)d_in[19];
    const float* ln2_b = (const float*)d_in[20];
    float* out = (float*)d_out;

    __half *ch, *ah, *wqb, *w1h, *w2h;
    float *fa, *fb, *fu, *scb;
    cudaGetSymbolAddress((void**)&ch,  g_comb);
    cudaGetSymbolAddress((void**)&ah,  g_act);
    cudaGetSymbolAddress((void**)&wqb, g_wq);
    cudaGetSymbolAddress((void**)&w1h, g_w1h);
    cudaGetSymbolAddress((void**)&w2h, g_w2h);
    cudaGetSymbolAddress((void**)&fa,  g_f32a);
    cudaGetSymbolAddress((void**)&fb,  g_f32b);
    cudaGetSymbolAddress((void**)&fu,  g_fused);
    cudaGetSymbolAddress((void**)&scb, g_scale);
    __half* wq0 = wqb;
    __half* wq1 = wqb + (size_t)F_DIM * F_DIM;
    __half* wq2 = wqb + 2 * (size_t)F_DIM * F_DIM;
    __half* wq3 = wqb + 3 * (size_t)F_DIM * F_DIM;

    cudaFuncSetAttribute(gemm_f16<0>, cudaFuncAttributeMaxDynamicSharedMemorySize, GEMM_SMEM_DYN);
    cudaFuncSetAttribute(gemm_f16<1>, cudaFuncAttributeMaxDynamicSharedMemorySize, GEMM_SMEM_DYN);

    // weight prep
    absmean_partial<<<dim3(64, 4), 256>>>(gate_w1, gate_w2, tr_w1, tr_w2);
    quantize_ternary<<<dim3(128, 4), 256>>>(gate_w1, gate_w2, tr_w1, tr_w2, wqb);
    convert_w<<<2048, 256>>>(mlp_w1, w1h, F2_DIM * F_DIM);
    convert_w<<<2048, 256>>>(mlp_w2, w2h, F_DIM * F2_DIM);
    build_combined<<<(B_ROWS * 512) / 256, 256>>>(zb, za, ze, zm, zs, ch);

    dim3 g2048(F_DIM / TILE_N, B_ROWS / TILE_M);   // (16, 64)
    dim3 g4096(F2_DIM / TILE_N, B_ROWS / TILE_M);  // (32, 64)

    // gate path (single fp16 pass; ternary weights exact in fp16)
    gemm_f16<0><<<g2048, 256, GEMM_SMEM_DYN>>>(ch, ch, wq0, wq0,
        1, F_DIM, F_DIM, 1.f, scb + 0, gate_b1, nullptr, ah);
    gemm_f16<1><<<g2048, 256, GEMM_SMEM_DYN>>>(ah, ah, wq1, wq1,
        1, F_DIM, F_DIM, 1.f, scb + 1, gate_b2, fa, nullptr);
    // transform path
    gemm_f16<0><<<g2048, 256, GEMM_SMEM_DYN>>>(ch, ch, wq2, wq2,
        1, F_DIM, F_DIM, 1.f, scb + 2, tr_b1, nullptr, ah);
    gemm_f16<1><<<g2048, 256, GEMM_SMEM_DYN>>>(ah, ah, wq3, wq3,
        1, F_DIM, F_DIM, 1.f, scb + 3, tr_b2, fb, nullptr);
    // sigmoid-gate fuse + ln1 (fused fp32 + fp16 copy reusing comb buffer)
    fused_sig_ln<<<B_ROWS, 256>>>(fa, fb, ln1_g, ln1_b, fu, ch);
    // mlp: single fp16 pass each (weight rounding ~2.8e-4/layer, inside budget)
    gemm_f16<0><<<g4096, 256, GEMM_SMEM_DYN>>>(ch, ch, w1h, w1h,
        1, F2_DIM, F_DIM, 1.f, nullptr, mlp_b1, nullptr, ah);
    gemm_f16<1><<<g2048, 256, GEMM_SMEM_DYN>>>(ah, ah, w2h, w2h,
        1, F_DIM, F2_DIM, 1.f, nullptr, mlp_b2, fa, nullptr);
    // residual + ln2
    final_ln<<<B_ROWS, 256>>>(fu, fa, ln2_g, ln2_b, out);
}

// round 12
// speedup vs baseline: 6.8475x; 1.0943x over previous
#include <cuda_runtime.h>
#include <cuda_fp16.h>
#include <cstdint>
#include <math.h>

#define B_ROWS 8192
#define F_DIM  2048
#define F2_DIM 4096
#define DB 512
#define DA 256
#define DE 256
#define DM 512
#define DS 512

// ---- device scratch (allocation forbidden) ----
__device__ __align__(256) __half g_comb[B_ROWS * F_DIM];
__device__ __align__(256) __half g_act [B_ROWS * F2_DIM];
__device__ __align__(256) float g_f32a [B_ROWS * F_DIM];
__device__ __align__(256) float g_f32b [B_ROWS * F_DIM];
__device__ __align__(256) float g_fused[B_ROWS * F_DIM];
__device__ __align__(256) __half g_wq[4 * F_DIM * F_DIM];
__device__ __align__(256) __half g_w1h[F2_DIM * F_DIM];
__device__ __align__(256) __half g_w2h[F_DIM * F2_DIM];
__device__ float g_partials[4 * 64];
__device__ float g_scale[4];

// ---- helpers (baseline PTX only: cp.async, ldmatrix, mma.sync f16) ----
__device__ __forceinline__ uint32_t smem_u32(const void* p) {
    uint32_t a;
    asm("{ .reg .u64 t; cvta.to.shared.u64 t, %1; cvt.u32.u64 %0, t; }" : "=r"(a) : "l"(p));
    return a;
}
__device__ __forceinline__ uint32_t sw128(uint32_t x) { return x ^ ((x >> 3) & 0x70); }
__device__ __forceinline__ void cp16(uint32_t dst, const void* src) {
    asm volatile("cp.async.cg.shared.global [%0], [%1], 16;\n" :: "r"(dst), "l"(src) : "memory");
}
__device__ __forceinline__ void cp_commit() { asm volatile("cp.async.commit_group;\n" ::: "memory"); }
template <int N> __device__ __forceinline__ void cp_wait() {
    asm volatile("cp.async.wait_group %0;\n" :: "n"(N) : "memory");
}
__device__ __forceinline__ void ldsm4(uint32_t* r, uint32_t a) {
    asm volatile("ldmatrix.sync.aligned.m8n8.x4.shared.b16 {%0,%1,%2,%3}, [%4];"
        : "=r"(r[0]), "=r"(r[1]), "=r"(r[2]), "=r"(r[3]) : "r"(a));
}
__device__ __forceinline__ void mma_f16(float* c, const uint32_t* a, uint32_t b0, uint32_t b1) {
    asm volatile("mma.sync.aligned.m16n8k16.row.col.f32.f16.f16.f32 "
        "{%0,%1,%2,%3}, {%4,%5,%6,%7}, {%8,%9}, {%0,%1,%2,%3};"
        : "+f"(c[0]), "+f"(c[1]), "+f"(c[2]), "+f"(c[3])
        : "r"(a[0]), "r"(a[1]), "r"(a[2]), "r"(a[3]), "r"(b0), "r"(b1));
}
__device__ __forceinline__ float gelu_erf(float h) {
    return 0.5f * h * (1.0f + erff(h * 0.70710678f));
}
__device__ __forceinline__ uint32_t packh2(float a, float b) {
    __half2 v; v.x = __float2half_rn(a); v.y = __float2half_rn(b);
    return *reinterpret_cast<uint32_t*>(&v);
}

// ---- fp16 GEMM: C[M,N] = A[M,K] @ B[N,K]^T, single pass ----
#define TILE_M 128
#define TILE_N 128
#define TILE_K 64
#define STAGE_BYTES (TILE_M * 128 + TILE_N * 128)   // 32KB
#define STAGES 3
#define GEMM_SMEM_DYN (STAGES * STAGE_BYTES + 1024)

__device__ __forceinline__ void load_tiles(uint32_t sa, uint32_t sb,
        const __half* A, const __half* Bm, int m0, int n0, int k0, int K, int tid) {
    const char* ab = (const char*)(A + (size_t)m0 * K + k0);
    const char* bb = (const char*)(Bm + (size_t)n0 * K + k0);
    size_t rb = (size_t)K * 2;
#pragma unroll
    for (int i = 0; i < 4; i++) {
        int t = tid + i * 256, row = t >> 3, ch = t & 7;
        cp16(sa + sw128(row * 128 + ch * 16), ab + (size_t)row * rb + ch * 16);
    }
#pragma unroll
    for (int i = 0; i < 4; i++) {
        int t = tid + i * 256, row = t >> 3, ch = t & 7;
        cp16(sb + sw128(row * 128 + ch * 16), bb + (size_t)row * rb + ch * 16);
    }
}

template <int EPI>  // 0: gelu -> fp16; 1: fp32 out
__global__ void __launch_bounds__(256, 2)
gemm_f16(const __half* A, const __half* B,
         int N, int K,
         const float* scale_ptr, const float* __restrict__ bias,
         float* outF, __half* outH) {
    extern __shared__ char smem[];
    uint32_t sbase = (smem_u32(smem) + 1023) & ~1023u;
    int tid = threadIdx.x, wid = tid >> 5, lane = tid & 31;
    int n0 = blockIdx.x * TILE_N, m0 = blockIdx.y * TILE_M;
    int wm = wid & 1, wn = wid >> 1;
    const int iters = K / TILE_K;

    for (int p = 0; p < 2 && p < iters; ++p) {
        uint32_t st = sbase + p * STAGE_BYTES;
        load_tiles(st, st + TILE_M * 128, A, B, m0, n0, p * TILE_K, K, tid);
        cp_commit();
    }

    float acc[4][4][4];
#pragma unroll
    for (int i = 0; i < 4; i++)
#pragma unroll
        for (int j = 0; j < 4; j++)
#pragma unroll
            for (int k = 0; k < 4; k++) acc[i][j][k] = 0.f;

    int q = lane >> 3, r = lane & 7;
    int aRow = wm * 64 + r + (q & 1) * 8;
    int aCol = (q >> 1) * 16;
    int bRow = wn * 32 + r + (q >> 1) * 8;
    int bCol = (q & 1) * 16;

    for (int it = 0; it < iters; ++it) {
        cp_wait<1>();
        __syncthreads();
        if (it + 2 < iters) {
            uint32_t st = sbase + ((it + 2) % STAGES) * STAGE_BYTES;
            load_tiles(st, st + TILE_M * 128, A, B, m0, n0, (it + 2) * TILE_K, K, tid);
        }
        cp_commit();
        uint32_t sA = sbase + (it % STAGES) * STAGE_BYTES;
        uint32_t sB = sA + TILE_M * 128;
#pragma unroll
        for (int ks = 0; ks < 4; ++ks) {
            uint32_t a[4][4], b[2][4];
#pragma unroll
            for (int mi = 0; mi < 4; ++mi)
                ldsm4(a[mi], sA + sw128((aRow + mi * 16) * 128 + aCol + ks * 32));
#pragma unroll
            for (int nj = 0; nj < 2; ++nj)
                ldsm4(b[nj], sB + sw128((bRow + nj * 16) * 128 + bCol + ks * 32));
#pragma unroll
            for (int mi = 0; mi < 4; ++mi)
#pragma unroll
                for (int n8 = 0; n8 < 4; ++n8)
                    mma_f16(acc[mi][n8], a[mi],
                            b[n8 >> 1][(n8 & 1) * 2], b[n8 >> 1][(n8 & 1) * 2 + 1]);
        }
    }

    float sc = scale_ptr ? *scale_ptr : 1.0f;
    int group = lane >> 2, tg = lane & 3;
#pragma unroll
    for (int mi = 0; mi < 4; ++mi) {
#pragma unroll
        for (int n8 = 0; n8 < 4; ++n8) {
            int row = m0 + wm * 64 + mi * 16 + group;
            int col = n0 + wn * 32 + n8 * 8 + tg * 2;
            float bb0 = bias[col], bb1 = bias[col + 1];
            float y0 = fmaf(sc, acc[mi][n8][0], bb0);
            float y1 = fmaf(sc, acc[mi][n8][1], bb1);
            float y2 = fmaf(sc, acc[mi][n8][2], bb0);
            float y3 = fmaf(sc, acc[mi][n8][3], bb1);
            if (EPI == 0) {
                *(uint32_t*)&outH[(size_t)row * N + col]       = packh2(gelu_erf(y0), gelu_erf(y1));
                *(uint32_t*)&outH[(size_t)(row + 8) * N + col] = packh2(gelu_erf(y2), gelu_erf(y3));
            } else {
                *(float2*)&outF[(size_t)row * N + col]       = make_float2(y0, y1);
                *(float2*)&outF[(size_t)(row + 8) * N + col] = make_float2(y2, y3);
            }
        }
    }
}

// ---- elementwise kernels ----
__device__ __forceinline__ float warpSum(float x) {
#pragma unroll
    for (int o = 16; o > 0; o >>= 1) x += __shfl_xor_sync(0xffffffffu, x, o);
    return x;
}

__global__ void absmean_partial(const float* w0, const float* w1, const float* w2, const float* w3) {
    const float* w = (blockIdx.y == 0) ? w0 : (blockIdx.y == 1) ? w1 : (blockIdx.y == 2) ? w2 : w3;
    const int chunk = (F_DIM * F_DIM) / 64;
    int base = blockIdx.x * chunk;
    float s = 0.f;
    for (int i = threadIdx.x; i < chunk; i += 256) s += fabsf(w[base + i]);
    __shared__ float red[8];
    s = warpSum(s);
    int wd = threadIdx.x >> 5, ln = threadIdx.x & 31;
    if (ln == 0) red[wd] = s;
    __syncthreads();
    if (wd == 0) {
        float v = (ln < 8) ? red[ln] : 0.f;
        v = warpSum(v);
        if (ln == 0) g_partials[blockIdx.y * 64 + blockIdx.x] = v;
    }
}

__global__ void quantize_ternary(const float* w0, const float* w1, const float* w2, const float* w3,
                                 __half* __restrict__ kq) {
    int slot = blockIdx.y;
    const float* w = (slot == 0) ? w0 : (slot == 1) ? w1 : (slot == 2) ? w2 : w3;
    __half* dst = kq + (size_t)slot * F_DIM * F_DIM;
    float sum = 0.f;
#pragma unroll
    for (int i = 0; i < 64; i++) sum += g_partials[slot * 64 + i];
    float s = sum * (1.0f / (float)(F_DIM * F_DIM));
    if (blockIdx.x == 0 && threadIdx.x == 0) g_scale[slot] = s;
    float inv = 1.0f / (s + 1e-5f);
    const int n4 = (F_DIM * F_DIM) / 4;
    int stride = gridDim.x * blockDim.x;
    for (int i = blockIdx.x * blockDim.x + threadIdx.x; i < n4; i += stride) {
        float4 v = reinterpret_cast<const float4*>(w)[i];
        float q0 = rintf(fminf(fmaxf(v.x * inv, -1.f), 1.f));
        float q1 = rintf(fminf(fmaxf(v.y * inv, -1.f), 1.f));
        float q2 = rintf(fminf(fmaxf(v.z * inv, -1.f), 1.f));
        float q3 = rintf(fminf(fmaxf(v.w * inv, -1.f), 1.f));
        uint2 u; u.x = packh2(q0, q1); u.y = packh2(q2, q3);
        reinterpret_cast<uint2*>(dst)[i] = u;
    }
}

__global__ void convert_w(const float* __restrict__ w, __half* __restrict__ hi, int n4) {
    int stride = gridDim.x * blockDim.x;
    for (int i = blockIdx.x * blockDim.x + threadIdx.x; i < n4; i += stride) {
        float4 v = reinterpret_cast<const float4*>(w)[i];
        uint2 u; u.x = packh2(v.x, v.y); u.y = packh2(v.z, v.w);
        reinterpret_cast<uint2*>(hi)[i] = u;
    }
}

__global__ void build_combined(const float* zb, const float* za, const float* ze,
                               const float* zm, const float* zs, __half* __restrict__ ch) {
    int idx = blockIdx.x * 256 + threadIdx.x;
    int r = idx >> 9;
    int c4 = (idx & 511) * 4;
    const float* src; int off;
    if      (c4 < DB)                { src = zb; off = r * DB + c4; }
    else if (c4 < DB + DA)           { src = za; off = r * DA + (c4 - DB); }
    else if (c4 < DB + DA + DE)      { src = ze; off = r * DE + (c4 - DB - DA); }
    else if (c4 < DB + DA + DE + DM) { src = zm; off = r * DM + (c4 - DB - DA - DE); }
    else                             { src = zs; off = r * DS + (c4 - DB - DA - DE - DM); }
    float4 v = *reinterpret_cast<const float4*>(src + off);
    uint2 u;
    u.x = packh2(v.x, v.y);
    u.y = packh2(v.z, v.w);
    *reinterpret_cast<uint2*>(&ch[(size_t)r * F_DIM + c4]) = u;
}

__global__ void fused_sig_ln(const float* __restrict__ g, const float* __restrict__ t,
                             const float* __restrict__ lg, const float* __restrict__ lb,
                             float* __restrict__ fused, __half* __restrict__ fh) {
    int row = blockIdx.x;
    size_t base = (size_t)row * F_DIM;
    float v[8], s1 = 0.f, s2 = 0.f;
#pragma unroll
    for (int i = 0; i < 8; i++) {
        int c = i * 256 + threadIdx.x;
        float gg = g[base + c], tt = t[base + c];
        float f = tt / (1.0f + expf(-1.2f * gg));
        v[i] = f; s1 += f; s2 += f * f;
    }
    __shared__ float rs[8], rq[8];
    int wd = threadIdx.x >> 5, ln = threadIdx.x & 31;
    float a = warpSum(s1), b = warpSum(s2);
    if (ln == 0) { rs[wd] = a; rq[wd] = b; }
    __syncthreads();
    if (wd == 0) {
        float x = (ln < 8) ? rs[ln] : 0.f;
        float y = (ln < 8) ? rq[ln] : 0.f;
        x = warpSum(x); y = warpSum(y);
        if (ln == 0) { rs[0] = x; rq[0] = y; }
    }
    __syncthreads();
    float mean = rs[0] * (1.0f / F_DIM);
    float var = rq[0] * (1.0f / F_DIM) - mean * mean;
    float inv = rsqrtf(var + 1e-5f);
#pragma unroll
    for (int i = 0; i < 8; i++) {
        int c = i * 256 + threadIdx.x;
        float y = (v[i] - mean) * inv * lg[c] + lb[c];
        fused[base + c] = y;
        fh[base + c] = __float2half_rn(y);
    }
}

__global__ void final_ln(const float* __restrict__ fused, const float* __restrict__ mlp,
                         const float* __restrict__ lg, const float* __restrict__ lb,
                         float* __restrict__ out) {
    int row = blockIdx.x;
    size_t base = (size_t)row * F_DIM;
    float v[8], s1 = 0.f, s2 = 0.f;
#pragma unroll
    for (int i = 0; i < 8; i++) {
        int c = i * 256 + threadIdx.x;
        float f = fused[base + c] + mlp[base + c];
        v[i] = f; s1 += f; s2 += f * f;
    }
    __shared__ float rs[8], rq[8];
    int wd = threadIdx.x >> 5, ln = threadIdx.x & 31;
    float a = warpSum(s1), b = warpSum(s2);
    if (ln == 0) { rs[wd] = a; rq[wd] = b; }
    __syncthreads();
    if (wd == 0) {
        float x = (ln < 8) ? rs[ln] : 0.f;
        float y = (ln < 8) ? rq[ln] : 0.f;
        x = warpSum(x); y = warpSum(y);
        if (ln == 0) { rs[0] = x; rq[0] = y; }
    }
    __syncthreads();
    float mean = rs[0] * (1.0f / F_DIM);
    float var = rq[0] * (1.0f / F_DIM) - mean * mean;
    float inv = rsqrtf(var + 1e-5f);
#pragma unroll
    for (int i = 0; i < 8; i++) {
        int c = i * 256 + threadIdx.x;
        out[base + c] = (v[i] - mean) * inv * lg[c] + lb[c];
    }
}

// ---- launch ----
extern "C" void kernel_launch(void* const* d_in, const int* in_sizes, int n_in,
                              void* d_out, int out_size) {
    (void)in_sizes; (void)n_in; (void)out_size;
    const float* zb = (const float*)d_in[0];
    const float* za = (const float*)d_in[1];
    const float* ze = (const float*)d_in[2];
    const float* zm = (const float*)d_in[3];
    const float* zs = (const float*)d_in[4];
    const float* gate_w1 = (const float*)d_in[5];
    const float* gate_b1 = (const float*)d_in[6];
    const float* gate_w2 = (const float*)d_in[7];
    const float* gate_b2 = (const float*)d_in[8];
    const float* tr_w1 = (const float*)d_in[9];
    const float* tr_b1 = (const float*)d_in[10];
    const float* tr_w2 = (const float*)d_in[11];
    const float* tr_b2 = (const float*)d_in[12];
    const float* mlp_w1 = (const float*)d_in[13];
    const float* mlp_b1 = (const float*)d_in[14];
    const float* mlp_w2 = (const float*)d_in[15];
    const float* mlp_b2 = (const float*)d_in[16];
    const float* ln1_g = (const float*)d_in[17];
    const float* ln1_b = (const float*)d_in[18];
    const float* ln2_g = (const float*)d_in[19];
    const float* ln2_b = (const float*)d_in[20];
    float* out = (float*)d_out;

    __half *ch, *ah, *wqb, *w1h, *w2h;
    float *fa, *fb, *fu, *scb;
    cudaGetSymbolAddress((void**)&ch,  g_comb);
    cudaGetSymbolAddress((void**)&ah,  g_act);
    cudaGetSymbolAddress((void**)&wqb, g_wq);
    cudaGetSymbolAddress((void**)&w1h, g_w1h);
    cudaGetSymbolAddress((void**)&w2h, g_w2h);
    cudaGetSymbolAddress((void**)&fa,  g_f32a);
    cudaGetSymbolAddress((void**)&fb,  g_f32b);
    cudaGetSymbolAddress((void**)&fu,  g_fused);
    cudaGetSymbolAddress((void**)&scb, g_scale);
    __half* wq0 = wqb;
    __half* wq1 = wqb + (size_t)F_DIM * F_DIM;
    __half* wq2 = wqb + 2 * (size_t)F_DIM * F_DIM;
    __half* wq3 = wqb + 3 * (size_t)F_DIM * F_DIM;

    cudaFuncSetAttribute(gemm_f16<0>, cudaFuncAttributeMaxDynamicSharedMemorySize, GEMM_SMEM_DYN);
    cudaFuncSetAttribute(gemm_f16<1>, cudaFuncAttributeMaxDynamicSharedMemorySize, GEMM_SMEM_DYN);

    // weight prep
    absmean_partial<<<dim3(64, 4), 256>>>(gate_w1, gate_w2, tr_w1, tr_w2);
    quantize_ternary<<<dim3(128, 4), 256>>>(gate_w1, gate_w2, tr_w1, tr_w2, wqb);
    convert_w<<<1024, 256>>>(mlp_w1, w1h, (F2_DIM * F_DIM) / 4);
    convert_w<<<1024, 256>>>(mlp_w2, w2h, (F_DIM * F2_DIM) / 4);
    build_combined<<<(B_ROWS * 512) / 256, 256>>>(zb, za, ze, zm, zs, ch);

    dim3 g2048(F_DIM / TILE_N, B_ROWS / TILE_M);   // (16, 64)
    dim3 g4096(F2_DIM / TILE_N, B_ROWS / TILE_M);  // (32, 64)

    // gate path (single fp16 pass; ternary weights exact in fp16)
    gemm_f16<0><<<g2048, 256, GEMM_SMEM_DYN>>>(ch, wq0, F_DIM, F_DIM, scb + 0, gate_b1, nullptr, ah);
    gemm_f16<1><<<g2048, 256, GEMM_SMEM_DYN>>>(ah, wq1, F_DIM, F_DIM, scb + 1, gate_b2, fa, nullptr);
    // transform path
    gemm_f16<0><<<g2048, 256, GEMM_SMEM_DYN>>>(ch, wq2, F_DIM, F_DIM, scb + 2, tr_b1, nullptr, ah);
    gemm_f16<1><<<g2048, 256, GEMM_SMEM_DYN>>>(ah, wq3, F_DIM, F_DIM, scb + 3, tr_b2, fb, nullptr);
    // sigmoid-gate fuse + ln1 (fused fp32 + fp16 copy reusing comb buffer)
    fused_sig_ln<<<B_ROWS, 256>>>(fa, fb, ln1_g, ln1_b, fu, ch);
    // mlp (single fp16 pass each)
    gemm_f16<0><<<g4096, 256, GEMM_SMEM_DYN>>>(ch, w1h, F2_DIM, F_DIM, nullptr, mlp_b1, nullptr, ah);
    gemm_f16<1><<<g2048, 256, GEMM_SMEM_DYN>>>(ah, w2h, F_DIM, F2_DIM, nullptr, mlp_b2, fa, nullptr);
    // residual + ln2
    final_ln<<<B_ROWS, 256>>>(fu, fa, ln2_g, ln2_b, out);
}

// round 13
// speedup vs baseline: 7.0657x; 1.0319x over previous
#include <cuda_runtime.h>
#include <cuda_fp16.h>
#include <cstdint>
#include <math.h>

#define B_ROWS 8192
#define F_DIM  2048
#define F2_DIM 4096
#define DB 512
#define DA 256
#define DE 256
#define DM 512
#define DS 512

// ---- device scratch (allocation forbidden) ----
__device__ __align__(256) __half g_comb[B_ROWS * F_DIM];
__device__ __align__(256) __half g_act [B_ROWS * F2_DIM];
__device__ __align__(256) float g_f32a [B_ROWS * F_DIM];
__device__ __align__(256) float g_f32b [B_ROWS * F_DIM];
__device__ __align__(256) float g_fused[B_ROWS * F_DIM];
__device__ __align__(256) __half g_wq[4 * F_DIM * F_DIM];   // slots: gate_w1, tr_w1, gate_w2, tr_w2
__device__ __align__(256) __half g_w1h[F2_DIM * F_DIM];
__device__ __align__(256) __half g_w2h[F_DIM * F2_DIM];
__device__ float g_partials[4 * 64];
__device__ float g_scale[4];

// ---- helpers (baseline PTX only: cp.async, ldmatrix, mma.sync f16) ----
__device__ __forceinline__ uint32_t smem_u32(const void* p) {
    uint32_t a;
    asm("{ .reg .u64 t; cvta.to.shared.u64 t, %1; cvt.u32.u64 %0, t; }" : "=r"(a) : "l"(p));
    return a;
}
__device__ __forceinline__ uint32_t sw128(uint32_t x) { return x ^ ((x >> 3) & 0x70); }
__device__ __forceinline__ void cp16(uint32_t dst, const void* src) {
    asm volatile("cp.async.cg.shared.global [%0], [%1], 16;\n" :: "r"(dst), "l"(src) : "memory");
}
__device__ __forceinline__ void cp_commit() { asm volatile("cp.async.commit_group;\n" ::: "memory"); }
template <int N> __device__ __forceinline__ void cp_wait() {
    asm volatile("cp.async.wait_group %0;\n" :: "n"(N) : "memory");
}
__device__ __forceinline__ void ldsm4(uint32_t* r, uint32_t a) {
    asm volatile("ldmatrix.sync.aligned.m8n8.x4.shared.b16 {%0,%1,%2,%3}, [%4];"
        : "=r"(r[0]), "=r"(r[1]), "=r"(r[2]), "=r"(r[3]) : "r"(a));
}
__device__ __forceinline__ void mma_f16(float* c, const uint32_t* a, uint32_t b0, uint32_t b1) {
    asm volatile("mma.sync.aligned.m16n8k16.row.col.f32.f16.f16.f32 "
        "{%0,%1,%2,%3}, {%4,%5,%6,%7}, {%8,%9}, {%0,%1,%2,%3};"
        : "+f"(c[0]), "+f"(c[1]), "+f"(c[2]), "+f"(c[3])
        : "r"(a[0]), "r"(a[1]), "r"(a[2]), "r"(a[3]), "r"(b0), "r"(b1));
}
__device__ __forceinline__ float gelu_erf(float h) {
    return 0.5f * h * (1.0f + erff(h * 0.70710678f));
}
__device__ __forceinline__ uint32_t packh2(float a, float b) {
    __half2 v; v.x = __float2half_rn(a); v.y = __float2half_rn(b);
    return *reinterpret_cast<uint32_t*>(&v);
}

// ---- fp16 GEMM (dual-capable): per-CTA n-half selects A window / B block / bias / scale / out ----
#define TILE_M 128
#define TILE_N 128
#define TILE_K 64
#define STAGE_BYTES (TILE_M * 128 + TILE_N * 128)   // 32KB
#define STAGES 3
#define GEMM_SMEM_DYN (STAGES * STAGE_BYTES + 1024)

__device__ __forceinline__ void load_tiles(uint32_t sa, uint32_t sb,
        const __half* Ab, const __half* Bt, int m0, int k0, int lda, int K, int tid) {
    const char* ab = (const char*)(Ab + (size_t)m0 * lda + k0);
    const char* bb = (const char*)(Bt + k0);
    size_t ra = (size_t)lda * 2, rb = (size_t)K * 2;
#pragma unroll
    for (int i = 0; i < 4; i++) {
        int t = tid + i * 256, row = t >> 3, ch = t & 7;
        cp16(sa + sw128(row * 128 + ch * 16), ab + (size_t)row * ra + ch * 16);
    }
#pragma unroll
    for (int i = 0; i < 4; i++) {
        int t = tid + i * 256, row = t >> 3, ch = t & 7;
        cp16(sb + sw128(row * 128 + ch * 16), bb + (size_t)row * rb + ch * 16);
    }
}

template <int EPI>  // 0: gelu -> fp16 (global col, stride outStride); 1: fp32 out (local col, stride F_DIM)
__global__ void __launch_bounds__(256, 2)
gemm_f16(const __half* A, int lda, int aoffHalf,
         const __half* Bbase, int K,
         const float* scales,
         const float* __restrict__ bias0, const float* __restrict__ bias1,
         float* outF0, float* outF1, __half* outH, int outStride) {
    extern __shared__ char smem[];
    uint32_t sbase = (smem_u32(smem) + 1023) & ~1023u;
    int tid = threadIdx.x, wid = tid >> 5, lane = tid & 31;
    int n0 = blockIdx.x * TILE_N, m0 = blockIdx.y * TILE_M;
    int half = (n0 >= F_DIM) ? 1 : 0;
    const __half* Ab = A + (half ? (size_t)aoffHalf : 0);
    const __half* Bt = Bbase + (size_t)n0 * K;
    const float* bias = half ? bias1 : bias0;
    float* outF = half ? outF1 : outF0;
    int colBiasOff = half * F_DIM;   // bias/outF use local column index
    int wm = wid & 1, wn = wid >> 1;
    const int iters = K / TILE_K;

    for (int p = 0; p < 2 && p < iters; ++p) {
        uint32_t st = sbase + p * STAGE_BYTES;
        load_tiles(st, st + TILE_M * 128, Ab, Bt, m0, p * TILE_K, lda, K, tid);
        cp_commit();
    }

    float acc[4][4][4];
#pragma unroll
    for (int i = 0; i < 4; i++)
#pragma unroll
        for (int j = 0; j < 4; j++)
#pragma unroll
            for (int k = 0; k < 4; k++) acc[i][j][k] = 0.f;

    int q = lane >> 3, r = lane & 7;
    int aRow = wm * 64 + r + (q & 1) * 8;
    int aCol = (q >> 1) * 16;
    int bRow = wn * 32 + r + (q >> 1) * 8;
    int bCol = (q & 1) * 16;

    for (int it = 0; it < iters; ++it) {
        cp_wait<1>();
        __syncthreads();
        if (it + 2 < iters) {
            uint32_t st = sbase + ((it + 2) % STAGES) * STAGE_BYTES;
            load_tiles(st, st + TILE_M * 128, Ab, Bt, m0, (it + 2) * TILE_K, lda, K, tid);
        }
        cp_commit();
        uint32_t sA = sbase + (it % STAGES) * STAGE_BYTES;
        uint32_t sB = sA + TILE_M * 128;
#pragma unroll
        for (int ks = 0; ks < 4; ++ks) {
            uint32_t a[4][4], b[2][4];
#pragma unroll
            for (int mi = 0; mi < 4; ++mi)
                ldsm4(a[mi], sA + sw128((aRow + mi * 16) * 128 + aCol + ks * 32));
#pragma unroll
            for (int nj = 0; nj < 2; ++nj)
                ldsm4(b[nj], sB + sw128((bRow + nj * 16) * 128 + bCol + ks * 32));
#pragma unroll
            for (int mi = 0; mi < 4; ++mi)
#pragma unroll
                for (int n8 = 0; n8 < 4; ++n8)
                    mma_f16(acc[mi][n8], a[mi],
                            b[n8 >> 1][(n8 & 1) * 2], b[n8 >> 1][(n8 & 1) * 2 + 1]);
        }
    }

    float sc = scales ? scales[half] : 1.0f;
    int group = lane >> 2, tg = lane & 3;
#pragma unroll
    for (int mi = 0; mi < 4; ++mi) {
#pragma unroll
        for (int n8 = 0; n8 < 4; ++n8) {
            int row = m0 + wm * 64 + mi * 16 + group;
            int col = n0 + wn * 32 + n8 * 8 + tg * 2;    // global col
            int cl = col - colBiasOff;                    // local col
            float bb0 = bias[cl], bb1 = bias[cl + 1];
            float y0 = fmaf(sc, acc[mi][n8][0], bb0);
            float y1 = fmaf(sc, acc[mi][n8][1], bb1);
            float y2 = fmaf(sc, acc[mi][n8][2], bb0);
            float y3 = fmaf(sc, acc[mi][n8][3], bb1);
            if (EPI == 0) {
                *(uint32_t*)&outH[(size_t)row * outStride + col]       = packh2(gelu_erf(y0), gelu_erf(y1));
                *(uint32_t*)&outH[(size_t)(row + 8) * outStride + col] = packh2(gelu_erf(y2), gelu_erf(y3));
            } else {
                *(float2*)&outF[(size_t)row * F_DIM + cl]       = make_float2(y0, y1);
                *(float2*)&outF[(size_t)(row + 8) * F_DIM + cl] = make_float2(y2, y3);
            }
        }
    }
}

// ---- elementwise kernels ----
__device__ __forceinline__ float warpSum(float x) {
#pragma unroll
    for (int o = 16; o > 0; o >>= 1) x += __shfl_xor_sync(0xffffffffu, x, o);
    return x;
}

__global__ void absmean_partial(const float* w0, const float* w1, const float* w2, const float* w3) {
    const float* w = (blockIdx.y == 0) ? w0 : (blockIdx.y == 1) ? w1 : (blockIdx.y == 2) ? w2 : w3;
    const int chunk = (F_DIM * F_DIM) / 64;
    int base = blockIdx.x * chunk;
    float s = 0.f;
    for (int i = threadIdx.x; i < chunk; i += 256) s += fabsf(w[base + i]);
    __shared__ float red[8];
    s = warpSum(s);
    int wd = threadIdx.x >> 5, ln = threadIdx.x & 31;
    if (ln == 0) red[wd] = s;
    __syncthreads();
    if (wd == 0) {
        float v = (ln < 8) ? red[ln] : 0.f;
        v = warpSum(v);
        if (ln == 0) g_partials[blockIdx.y * 64 + blockIdx.x] = v;
    }
}

__global__ void quantize_ternary(const float* w0, const float* w1, const float* w2, const float* w3,
                                 __half* __restrict__ kq) {
    int slot = blockIdx.y;
    const float* w = (slot == 0) ? w0 : (slot == 1) ? w1 : (slot == 2) ? w2 : w3;
    __half* dst = kq + (size_t)slot * F_DIM * F_DIM;
    float sum = 0.f;
#pragma unroll
    for (int i = 0; i < 64; i++) sum += g_partials[slot * 64 + i];
    float s = sum * (1.0f / (float)(F_DIM * F_DIM));
    if (blockIdx.x == 0 && threadIdx.x == 0) g_scale[slot] = s;
    float inv = 1.0f / (s + 1e-5f);
    const int n4 = (F_DIM * F_DIM) / 4;
    int stride = gridDim.x * blockDim.x;
    for (int i = blockIdx.x * blockDim.x + threadIdx.x; i < n4; i += stride) {
        float4 v = reinterpret_cast<const float4*>(w)[i];
        float q0 = rintf(fminf(fmaxf(v.x * inv, -1.f), 1.f));
        float q1 = rintf(fminf(fmaxf(v.y * inv, -1.f), 1.f));
        float q2 = rintf(fminf(fmaxf(v.z * inv, -1.f), 1.f));
        float q3 = rintf(fminf(fmaxf(v.w * inv, -1.f), 1.f));
        uint2 u; u.x = packh2(q0, q1); u.y = packh2(q2, q3);
        reinterpret_cast<uint2*>(dst)[i] = u;
    }
}

__global__ void convert_w(const float* __restrict__ wa, __half* __restrict__ ha,
                          const float* __restrict__ wb, __half* __restrict__ hb, int n4) {
    const float* w = blockIdx.y ? wb : wa;
    __half* h = blockIdx.y ? hb : ha;
    int stride = gridDim.x * blockDim.x;
    for (int i = blockIdx.x * blockDim.x + threadIdx.x; i < n4; i += stride) {
        float4 v = reinterpret_cast<const float4*>(w)[i];
        uint2 u; u.x = packh2(v.x, v.y); u.y = packh2(v.z, v.w);
        reinterpret_cast<uint2*>(h)[i] = u;
    }
}

__global__ void build_combined(const float* zb, const float* za, const float* ze,
                               const float* zm, const float* zs, __half* __restrict__ ch) {
    int idx = blockIdx.x * 256 + threadIdx.x;
    int r = idx >> 9;
    int c4 = (idx & 511) * 4;
    const float* src; int off;
    if      (c4 < DB)                { src = zb; off = r * DB + c4; }
    else if (c4 < DB + DA)           { src = za; off = r * DA + (c4 - DB); }
    else if (c4 < DB + DA + DE)      { src = ze; off = r * DE + (c4 - DB - DA); }
    else if (c4 < DB + DA + DE + DM) { src = zm; off = r * DM + (c4 - DB - DA - DE); }
    else                             { src = zs; off = r * DS + (c4 - DB - DA - DE - DM); }
    float4 v = *reinterpret_cast<const float4*>(src + off);
    uint2 u;
    u.x = packh2(v.x, v.y);
    u.y = packh2(v.z, v.w);
    *reinterpret_cast<uint2*>(&ch[(size_t)r * F_DIM + c4]) = u;
}

__global__ void fused_sig_ln(const float* __restrict__ g, const float* __restrict__ t,
                             const float* __restrict__ lg, const float* __restrict__ lb,
                             float* __restrict__ fused, __half* __restrict__ fh) {
    int row = blockIdx.x;
    size_t base = (size_t)row * F_DIM;
    float v[8], s1 = 0.f, s2 = 0.f;
#pragma unroll
    for (int i = 0; i < 8; i++) {
        int c = i * 256 + threadIdx.x;
        float gg = g[base + c], tt = t[base + c];
        float f = tt / (1.0f + expf(-1.2f * gg));
        v[i] = f; s1 += f; s2 += f * f;
    }
    __shared__ float rs[8], rq[8];
    int wd = threadIdx.x >> 5, ln = threadIdx.x & 31;
    float a = warpSum(s1), b = warpSum(s2);
    if (ln == 0) { rs[wd] = a; rq[wd] = b; }
    __syncthreads();
    if (wd == 0) {
        float x = (ln < 8) ? rs[ln] : 0.f;
        float y = (ln < 8) ? rq[ln] : 0.f;
        x = warpSum(x); y = warpSum(y);
        if (ln == 0) { rs[0] = x; rq[0] = y; }
    }
    __syncthreads();
    float mean = rs[0] * (1.0f / F_DIM);
    float var = rq[0] * (1.0f / F_DIM) - mean * mean;
    float inv = rsqrtf(var + 1e-5f);
#pragma unroll
    for (int i = 0; i < 8; i++) {
        int c = i * 256 + threadIdx.x;
        float y = (v[i] - mean) * inv * lg[c] + lb[c];
        fused[base + c] = y;
        fh[base + c] = __float2half_rn(y);
    }
}

__global__ void final_ln(const float* __restrict__ fused, const float* __restrict__ mlp,
                         const float* __restrict__ lg, const float* __restrict__ lb,
                         float* __restrict__ out) {
    int row = blockIdx.x;
    size_t base = (size_t)row * F_DIM;
    float v[8], s1 = 0.f, s2 = 0.f;
#pragma unroll
    for (int i = 0; i < 8; i++) {
        int c = i * 256 + threadIdx.x;
        float f = fused[base + c] + mlp[base + c];
        v[i] = f; s1 += f; s2 += f * f;
    }
    __shared__ float rs[8], rq[8];
    int wd = threadIdx.x >> 5, ln = threadIdx.x & 31;
    float a = warpSum(s1), b = warpSum(s2);
    if (ln == 0) { rs[wd] = a; rq[wd] = b; }
    __syncthreads();
    if (wd == 0) {
        float x = (ln < 8) ? rs[ln] : 0.f;
        float y = (ln < 8) ? rq[ln] : 0.f;
        x = warpSum(x); y = warpSum(y);
        if (ln == 0) { rs[0] = x; rq[0] = y; }
    }
    __syncthreads();
    float mean = rs[0] * (1.0f / F_DIM);
    float var = rq[0] * (1.0f / F_DIM) - mean * mean;
    float inv = rsqrtf(var + 1e-5f);
#pragma unroll
    for (int i = 0; i < 8; i++) {
        int c = i * 256 + threadIdx.x;
        out[base + c] = (v[i] - mean) * inv * lg[c] + lb[c];
    }
}

// ---- launch ----
extern "C" void kernel_launch(void* const* d_in, const int* in_sizes, int n_in,
                              void* d_out, int out_size) {
    (void)in_sizes; (void)n_in; (void)out_size;
    const float* zb = (const float*)d_in[0];
    const float* za = (const float*)d_in[1];
    const float* ze = (const float*)d_in[2];
    const float* zm = (const float*)d_in[3];
    const float* zs = (const float*)d_in[4];
    const float* gate_w1 = (const float*)d_in[5];
    const float* gate_b1 = (const float*)d_in[6];
    const float* gate_w2 = (const float*)d_in[7];
    const float* gate_b2 = (const float*)d_in[8];
    const float* tr_w1 = (const float*)d_in[9];
    const float* tr_b1 = (const float*)d_in[10];
    const float* tr_w2 = (const float*)d_in[11];
    const float* tr_b2 = (const float*)d_in[12];
    const float* mlp_w1 = (const float*)d_in[13];
    const float* mlp_b1 = (const float*)d_in[14];
    const float* mlp_w2 = (const float*)d_in[15];
    const float* mlp_b2 = (const float*)d_in[16];
    const float* ln1_g = (const float*)d_in[17];
    const float* ln1_b = (const float*)d_in[18];
    const float* ln2_g = (const float*)d_in[19];
    const float* ln2_b = (const float*)d_in[20];
    float* out = (float*)d_out;

    __half *ch, *ah, *wqb, *w1h, *w2h;
    float *fa, *fb, *fu, *scb;
    cudaGetSymbolAddress((void**)&ch,  g_comb);
    cudaGetSymbolAddress((void**)&ah,  g_act);
    cudaGetSymbolAddress((void**)&wqb, g_wq);
    cudaGetSymbolAddress((void**)&w1h, g_w1h);
    cudaGetSymbolAddress((void**)&w2h, g_w2h);
    cudaGetSymbolAddress((void**)&fa,  g_f32a);
    cudaGetSymbolAddress((void**)&fb,  g_f32b);
    cudaGetSymbolAddress((void**)&fu,  g_fused);
    cudaGetSymbolAddress((void**)&scb, g_scale);

    cudaFuncSetAttribute(gemm_f16<0>, cudaFuncAttributeMaxDynamicSharedMemorySize, GEMM_SMEM_DYN);
    cudaFuncSetAttribute(gemm_f16<1>, cudaFuncAttributeMaxDynamicSharedMemorySize, GEMM_SMEM_DYN);

    // weight prep (slot order: gate_w1, tr_w1, gate_w2, tr_w2 — layer-stacked)
    absmean_partial<<<dim3(64, 4), 256>>>(gate_w1, tr_w1, gate_w2, tr_w2);
    quantize_ternary<<<dim3(128, 4), 256>>>(gate_w1, tr_w1, gate_w2, tr_w2, wqb);
    convert_w<<<dim3(512, 2), 256>>>(mlp_w1, w1h, mlp_w2, w2h, (F2_DIM * F_DIM) / 4);
    build_combined<<<(B_ROWS * 512) / 256, 256>>>(zb, za, ze, zm, zs, ch);

    dim3 gDual(F2_DIM / TILE_N, B_ROWS / TILE_M);  // (32, 64)
    dim3 gHalf(F_DIM / TILE_N, B_ROWS / TILE_M);   // (16, 64)

    // layer-1 dual: gate1 + tr1 (shared A; stacked weights slots 0-1; gelu -> act [8192,4096])
    gemm_f16<0><<<gDual, 256, GEMM_SMEM_DYN>>>(ch, F_DIM, 0, wqb, F_DIM,
        scb + 0, gate_b1, tr_b1, nullptr, nullptr, ah, F2_DIM);
    // layer-2 dual: gate2 + tr2 (per-half A window; stacked weights slots 2-3; fp32 -> fa / fb)
    gemm_f16<1><<<gDual, 256, GEMM_SMEM_DYN>>>(ah, F2_DIM, F_DIM, wqb + 2 * (size_t)F_DIM * F_DIM, F_DIM,
        scb + 2, gate_b2, tr_b2, fa, fb, nullptr, 0);
    // sigmoid-gate fuse + ln1 (fused fp32 + fp16 copy reusing comb buffer)
    fused_sig_ln<<<B_ROWS, 256>>>(fa, fb, ln1_g, ln1_b, fu, ch);
    // mlp1 (gelu -> act [8192,4096]); bias1 = mlp_b1 + 2048 for local indexing
    gemm_f16<0><<<gDual, 256, GEMM_SMEM_DYN>>>(ch, F_DIM, 0, w1h, F_DIM,
        nullptr, mlp_b1, mlp_b1 + F_DIM, nullptr, nullptr, ah, F2_DIM);
    // mlp2 (K=4096, fp32 -> fa)
    gemm_f16<1><<<gHalf, 256, GEMM_SMEM_DYN>>>(ah, F2_DIM, 0, w2h, F2_DIM,
        nullptr, mlp_b2, mlp_b2, fa, fa, nullptr, 0);
    // residual + ln2
    final_ln<<<B_ROWS, 256>>>(fu, fa, ln2_g, ln2_b, out);
}